// round 10
// baseline (speedup 1.0000x reference)
#include <cuda_runtime.h>
#include <cuda_fp16.h>
#include <cuda_fp8.h>
#include <math.h>
#include <stdint.h>

// Problem constants
#define NB 4
#define NS 4096
#define ND 512
#define NO 4
#define NLAYER 4
#define NF 2048
#define NT (NB*NS)
#define NCHUNK 32
#define CLEN 128

#define A8SCALE (1.0f/256.0f)
#define B8SCALE 256.0f

// ---------------- scratch (static device globals) ----------------------------
__device__ __align__(256) float  d_h[(size_t)NT * ND];
__device__ __align__(256) float4 d_proj[NT];
__device__ __align__(256) float4 d_end[NB * NCHUNK * ND];
// activation buffers: fp16 hi + fp8 (scaled 1/256) copies
__device__ __align__(256) __half d_th[(size_t)NT*ND];
__device__ __align__(256) unsigned char d_t8[(size_t)NT*ND];
__device__ __align__(256) __half d_gh[(size_t)NT*NF];
__device__ __align__(256) unsigned char d_g8[(size_t)NT*NF];
__device__ __align__(256) __half d_hl4[NLAYER][(size_t)NT*ND];
// transposed weights: [N,K] K-major; hi fp16, lo fp8 (scaled 256)
__device__ __align__(256) __half d_w1h[(size_t)NLAYER*NF*ND];
__device__ __align__(256) unsigned char d_w1l8[(size_t)NLAYER*NF*ND];
__device__ __align__(256) __half d_w2h[(size_t)NLAYER*ND*NF];
__device__ __align__(256) unsigned char d_w2l8[(size_t)NLAYER*ND*NF];
// folded head weights
__device__ __align__(256) float d_skW[NLAYER*ND*3];
__device__ __align__(256) float d_cst[3];

// ---------------- helpers ----------------------------------------------------
__device__ __forceinline__ uint32_t smem_u32(const void* p) {
    uint32_t a;
    asm("{ .reg .u64 t; cvta.to.shared.u64 t, %1; cvt.u32.u64 %0, t; }" : "=r"(a) : "l"(p));
    return a;
}
__device__ __forceinline__ void cpasync16(uint32_t s, const void* g) {
    asm volatile("cp.async.cg.shared.global [%0], [%1], 16;" :: "r"(s), "l"(g));
}
__device__ __forceinline__ void ldmx4(uint32_t& r0, uint32_t& r1, uint32_t& r2,
                                      uint32_t& r3, uint32_t addr) {
    asm volatile("ldmatrix.sync.aligned.m8n8.x4.shared.b16 {%0,%1,%2,%3}, [%4];"
        : "=r"(r0), "=r"(r1), "=r"(r2), "=r"(r3) : "r"(addr));
}
__device__ __forceinline__ void split2h(float v, __half& h, __half& l) {
    h = __float2half_rn(v);
    l = __float2half_rn(v - __half2float(h));
}
__device__ __forceinline__ float gelu_exact(float x) {
    return 0.5f * x * (1.0f + erff(x * 0.70710678118654752440f));
}
__device__ __forceinline__ float warpReduceSum(float v) {
    #pragma unroll
    for (int o = 16; o > 0; o >>= 1) v += __shfl_xor_sync(0xffffffffu, v, o);
    return v;
}
__device__ __forceinline__ unsigned char to_e4m3(float v) {
    return (unsigned char)__nv_cvt_float_to_fp8(v, __NV_SATFINITE, __NV_E4M3);
}
// fp16 hi product, fp32 acc
__device__ __forceinline__ void mma16816(float* c, uint32_t a0, uint32_t a1,
                                         uint32_t a2, uint32_t a3,
                                         uint32_t b0, uint32_t b1) {
    asm volatile("mma.sync.aligned.m16n8k16.row.col.f32.f16.f16.f32 "
        "{%0,%1,%2,%3}, {%4,%5,%6,%7}, {%8,%9}, {%0,%1,%2,%3};"
        : "+f"(c[0]), "+f"(c[1]), "+f"(c[2]), "+f"(c[3])
        : "r"(a0), "r"(a1), "r"(a2), "r"(a3), "r"(b0), "r"(b1));
}
// e4m3 correction product, K=32 per instruction, same C fragment layout
__device__ __forceinline__ void mma16832f8(float* c, uint32_t a0, uint32_t a1,
                                           uint32_t a2, uint32_t a3,
                                           uint32_t b0, uint32_t b1) {
    asm volatile("mma.sync.aligned.m16n8k32.row.col.f32.e4m3.e4m3.f32 "
        "{%0,%1,%2,%3}, {%4,%5,%6,%7}, {%8,%9}, {%0,%1,%2,%3};"
        : "+f"(c[0]), "+f"(c[1]), "+f"(c[2]), "+f"(c[3])
        : "r"(a0), "r"(a1), "r"(a2), "r"(a3), "r"(b0), "r"(b1));
}

// ---------------- weight transpose + split: w[K,N] -> hi fp16 / lo8 e4m3 -----
__global__ void wsplitT(const float* __restrict__ w, __half* __restrict__ hi,
                        unsigned char* __restrict__ lo8, int K, int N) {
    __shared__ float t[32][33];
    size_t loff = (size_t)blockIdx.z * K * N;
    int n0 = blockIdx.x * 32, k0 = blockIdx.y * 32;
    int tx = threadIdx.x, ty = threadIdx.y;   // (32,8)
    #pragma unroll
    for (int j = 0; j < 4; j++) {
        int r = ty * 4 + j;
        t[r][tx] = w[loff + (size_t)(k0 + r) * N + n0 + tx];
    }
    __syncthreads();
    #pragma unroll
    for (int j = 0; j < 4; j++) {
        int r = ty * 4 + j;
        float v = t[tx][r];
        __half h, l; split2h(v, h, l);
        size_t oi = loff + (size_t)(n0 + r) * K + k0 + tx;
        hi[oi] = h;
        lo8[oi] = to_e4m3(__half2float(l) * B8SCALE);
    }
}

// ---------------- fold skip weights: skW = skip_w @ out_w (warp per (l,d)) ---
__global__ void skw_prep(const float* __restrict__ skip_w, const float* __restrict__ ow) {
    int w = (blockIdx.x * blockDim.x + threadIdx.x) >> 5;
    int lane = threadIdx.x & 31;
    int l = w >> 9, d = w & (ND-1);
    const float* wr = skip_w + ((size_t)l * ND + d) * ND;
    float s0 = 0.f, s1 = 0.f, s2 = 0.f;
    for (int n = lane; n < ND; n += 32) {
        float v = wr[n];
        const float* o = ow + n * 3;
        s0 += v * o[0]; s1 += v * o[1]; s2 += v * o[2];
    }
    s0 = warpReduceSum(s0); s1 = warpReduceSum(s1); s2 = warpReduceSum(s2);
    if (lane == 0) {
        float* dst = d_skW + (l * ND + d) * 3;
        dst[0] = s0; dst[1] = s1; dst[2] = s2;
    }
}
__global__ void cst_prep(const float* __restrict__ skip_b, const float* __restrict__ ow,
                         const float* __restrict__ ob) {
    int j = threadIdx.x >> 5, lane = threadIdx.x & 31;   // 3 warps
    if (j >= 3) return;
    float s = 0.f;
    for (int ln = lane; ln < NLAYER*ND; ln += 32)
        s += skip_b[ln] * ow[(ln & (ND-1)) * 3 + j];
    s = warpReduceSum(s);
    if (lane == 0) d_cst[j] = s + ob[j];
}

// ---------------- embed ------------------------------------------------------
__global__ void embed_kernel(const float* __restrict__ x, const float* __restrict__ ew,
                             const float* __restrict__ eb, const float* __restrict__ pe) {
    int t = blockIdx.x, tid = threadIdx.x;
    int s = t & (NS - 1);
    float x0 = x[t*4+0], x1 = x[t*4+1], x2 = x[t*4+2], x3 = x[t*4+3];
    float4 e0 = ((const float4*)(ew        ))[tid];
    float4 e1 = ((const float4*)(ew +   ND))[tid];
    float4 e2 = ((const float4*)(ew + 2*ND))[tid];
    float4 e3 = ((const float4*)(ew + 3*ND))[tid];
    float4 bb = ((const float4*)eb)[tid];
    float4 pp = ((const float4*)(pe + (size_t)s*ND))[tid];
    float4 r;
    r.x = x0*e0.x + x1*e1.x + x2*e2.x + x3*e3.x + bb.x + pp.x;
    r.y = x0*e0.y + x1*e1.y + x2*e2.y + x3*e3.y + bb.y + pp.y;
    r.z = x0*e0.z + x1*e1.z + x2*e2.z + x3*e3.z + bb.z + pp.z;
    r.w = x0*e0.w + x1*e1.w + x2*e2.w + x3*e3.w + bb.w + pp.w;
    ((float4*)(d_h + (size_t)t*ND))[tid] = r;
}

// ---------------- fused LN1 + hyena projection (warp-per-token) --------------
__global__ void ln1_proj_kernel(const float* __restrict__ w, const float* __restrict__ bta,
                                const float* __restrict__ P) {
    int wi = threadIdx.x >> 5, lane = threadIdx.x & 31;
    int t = blockIdx.x * 4 + wi;
    const float4* hrow = (const float4*)(d_h + (size_t)t * ND);
    float4 v[4];
    float sum = 0.f;
    #pragma unroll
    for (int j = 0; j < 4; j++) {
        v[j] = hrow[lane + j*32];
        sum += v[j].x + v[j].y + v[j].z + v[j].w;
    }
    float mu = warpReduceSum(sum) * (1.0f/ND);
    float sq = 0.f;
    #pragma unroll
    for (int j = 0; j < 4; j++) {
        float a0=v[j].x-mu, a1=v[j].y-mu, a2=v[j].z-mu, a3=v[j].w-mu;
        sq += a0*a0 + a1*a1 + a2*a2 + a3*a3;
    }
    float rs = rsqrtf(warpReduceSum(sq) * (1.0f/ND) + 1e-5f);
    float p0=0.f, p1=0.f, p2=0.f, p3=0.f;
    #pragma unroll
    for (int j = 0; j < 4; j++) {
        int f4 = lane + j*32;
        float4 wv = ((const float4*)w)[f4];
        float4 bv = ((const float4*)bta)[f4];
        float n0=(v[j].x-mu)*rs*wv.x+bv.x, n1=(v[j].y-mu)*rs*wv.y+bv.y;
        float n2=(v[j].z-mu)*rs*wv.z+bv.z, n3=(v[j].w-mu)*rs*wv.w+bv.w;
        float4 q0 = ((const float4*)(P       ))[f4];
        float4 q1 = ((const float4*)(P +   ND))[f4];
        float4 q2 = ((const float4*)(P + 2*ND))[f4];
        float4 q3 = ((const float4*)(P + 3*ND))[f4];
        p0 += n0*q0.x + n1*q0.y + n2*q0.z + n3*q0.w;
        p1 += n0*q1.x + n1*q1.y + n2*q1.z + n3*q1.w;
        p2 += n0*q2.x + n1*q2.y + n2*q2.z + n3*q2.w;
        p3 += n0*q3.x + n1*q3.y + n2*q3.z + n3*q3.w;
    }
    p0 = warpReduceSum(p0); p1 = warpReduceSum(p1);
    p2 = warpReduceSum(p2); p3 = warpReduceSum(p3);
    if (lane == 0) d_proj[t] = make_float4(p0, p1, p2, p3);
}

// ---------------- hyena scan -------------------------------------------------
__global__ void hyena_pass1(const float* __restrict__ coef) {
    int tid = blockIdx.x * blockDim.x + threadIdx.x;
    int d = tid & (ND-1);
    int k = (tid >> 9) & (NCHUNK-1);
    int b = tid >> 14;
    float l0 = expf(coef[0*ND+d]), l1 = expf(coef[1*ND+d]);
    float l2 = expf(coef[2*ND+d]), l3 = expf(coef[3*ND+d]);
    float c0=0.f, c1=0.f, c2=0.f, c3=0.f;
    int base = b*NS + k*CLEN;
    #pragma unroll 4
    for (int j = 0; j < CLEN; j++) {
        float4 p = d_proj[base + j];
        c0 = c0*l0 + p.x; c1 = c1*l1 + p.y;
        c2 = c2*l2 + p.z; c3 = c3*l3 + p.w;
    }
    d_end[(b*NCHUNK + k)*ND + d] = make_float4(c0, c1, c2, c3);
}

// pass3 with inlined chunk-combine (former pass2): carry-in from d_end
__global__ void hyena_pass3(const float* __restrict__ coef) {
    int tid = blockIdx.x * blockDim.x + threadIdx.x;
    int d = tid & (ND-1);
    int k = (tid >> 9) & (NCHUNK-1);
    int b = tid >> 14;
    float l0 = expf(coef[0*ND+d]), l1 = expf(coef[1*ND+d]);
    float l2 = expf(coef[2*ND+d]), l3 = expf(coef[3*ND+d]);
    float L0 = expf(coef[0*ND+d]*(float)CLEN), L1 = expf(coef[1*ND+d]*(float)CLEN);
    float L2 = expf(coef[2*ND+d]*(float)CLEN), L3 = expf(coef[3*ND+d]*(float)CLEN);
    float4 c = make_float4(0.f, 0.f, 0.f, 0.f);
    for (int j = 0; j < k; j++) {
        float4 e = d_end[(b*NCHUNK + j)*ND + d];
        c.x = c.x*L0 + e.x; c.y = c.y*L1 + e.y;
        c.z = c.z*L2 + e.z; c.w = c.w*L3 + e.w;
    }
    int base = b*NS + k*CLEN;
    #pragma unroll 4
    for (int j = 0; j < CLEN; j++) {
        float4 p = d_proj[base + j];
        c.x = c.x*l0 + p.x; c.y = c.y*l1 + p.y;
        c.z = c.z*l2 + p.z; c.w = c.w*l3 + p.w;
        size_t idx = (size_t)(base + j)*ND + d;
        d_h[idx] += c.x + c.y + c.z + c.w;
    }
}

// ---------------- LN2 (warp-per-token): h -> fp16 d_th + fp8 d_t8 ------------
__global__ void ln2_kernel(const float* __restrict__ w, const float* __restrict__ bta) {
    int wi = threadIdx.x >> 5, lane = threadIdx.x & 31;
    int t = blockIdx.x * 4 + wi;
    const float4* hrow = (const float4*)(d_h + (size_t)t * ND);
    float4 v[4];
    float sum = 0.f;
    #pragma unroll
    for (int j = 0; j < 4; j++) {
        v[j] = hrow[lane + j*32];
        sum += v[j].x + v[j].y + v[j].z + v[j].w;
    }
    float mu = warpReduceSum(sum) * (1.0f/ND);
    float sq = 0.f;
    #pragma unroll
    for (int j = 0; j < 4; j++) {
        float a0=v[j].x-mu, a1=v[j].y-mu, a2=v[j].z-mu, a3=v[j].w-mu;
        sq += a0*a0 + a1*a1 + a2*a2 + a3*a3;
    }
    float rs = rsqrtf(warpReduceSum(sq) * (1.0f/ND) + 1e-5f);
    size_t trow = (size_t)t * ND;
    #pragma unroll
    for (int j = 0; j < 4; j++) {
        int f4 = lane + j*32;
        float4 wv = ((const float4*)w)[f4];
        float4 bv = ((const float4*)bta)[f4];
        float r0=(v[j].x-mu)*rs*wv.x+bv.x, r1=(v[j].y-mu)*rs*wv.y+bv.y;
        float r2=(v[j].z-mu)*rs*wv.z+bv.z, r3=(v[j].w-mu)*rs*wv.w+bv.w;
        *(__half2*)(d_th + trow + f4*4    ) =
            __halves2half2(__float2half_rn(r0), __float2half_rn(r1));
        *(__half2*)(d_th + trow + f4*4 + 2) =
            __halves2half2(__float2half_rn(r2), __float2half_rn(r3));
        uint32_t q = (uint32_t)to_e4m3(r0*A8SCALE)
                   | ((uint32_t)to_e4m3(r1*A8SCALE) << 8)
                   | ((uint32_t)to_e4m3(r2*A8SCALE) << 16)
                   | ((uint32_t)to_e4m3(r3*A8SCALE) << 24);
        *(uint32_t*)(d_t8 + trow + f4*4) = q;
    }
}

// ---------------- mixed fp16/fp8 HMMA GEMM -----------------------------------
// C = Ah(fp16)*Bh(fp16)^T [k16] + A8(e4m3)*Bl8(e4m3)^T [k32], fp32 acc shared.
// MODE 0: gelu(acc+bias) -> Ch fp16 + C8 fp8
// MODE 1: r = acc+bias+Cf; Cf=r; Ch=fp16(r)
// MODE 2: r = acc+bias+Cf; (no Cf write) Ch=fp16(r)
#define SAB   80                 // fp16 row: 64B data + 16 pad
#define BUFB  (128*SAB)          // 10240
#define SA8   48                 // fp8 row: 32B data + 16 pad
#define BUF8  (128*SA8)          // 6144
#define STGB  (2*BUFB + 2*BUF8)  // Ah, Bh, A8, Bl8 = 32768
#define GSMEM (2*STGB)           // 65536

template<int MODE>
__global__ void __launch_bounds__(256, 2)
hgemm(const __half* __restrict__ Ah, const unsigned char* __restrict__ A8,
      const __half* __restrict__ Bh, const unsigned char* __restrict__ Bl8,
      const float* __restrict__ bias, int N, int K,
      float* __restrict__ Cf, __half* __restrict__ Ch, unsigned char* __restrict__ C8)
{
    extern __shared__ char smem[];
    const int tid = threadIdx.x, lane = tid & 31, w = tid >> 5;
    const int wm = w >> 2, wn = w & 3;
    const int bx = blockIdx.x, by = blockIdx.y;
    const int nK = K >> 5;
    const uint32_t sb0 = smem_u32(smem);

    // fp16 ldmatrix offsets (rows stride SAB)
    const uint32_t a_off = (uint32_t)(wm*64 + (lane & 7) + ((lane >> 3) & 1) * 8) * SAB
                         + ((lane >> 4) & 1) * 16;
    const uint32_t b_off = (uint32_t)(wn*32 + (lane & 7) + ((lane >> 4) & 1) * 8) * SAB
                         + ((lane >> 3) & 1) * 16;
    // fp8 b16-view ldmatrix offsets (rows stride SA8; 16B half = kk 8..15)
    const uint32_t a8_off = (uint32_t)(wm*64 + (lane & 7) + ((lane >> 3) & 1) * 8) * SA8
                          + ((lane >> 4) & 1) * 16;
    const uint32_t b8_off = (uint32_t)(wn*32 + (lane & 7) + ((lane >> 4) & 1) * 8) * SA8
                          + ((lane >> 3) & 1) * 16;

    const int lr = tid >> 2, lc8 = tid & 3;       // fp16 loader: 64 rows x 4 chunks
    const int l8r = tid >> 1, c8 = tid & 1;       // fp8 loader: 128 rows x 2 chunks
    #define LD_STAGE(s, kk) do {                                                 \
        uint32_t _b = sb0 + (s) * STGB;                                          \
        _Pragma("unroll")                                                        \
        for (int _i = 0; _i < 2; _i++) {                                         \
            int _r = lr + _i * 64;                                               \
            uint32_t _o = _r * SAB + lc8 * 16;                                   \
            size_t _ar = (size_t)(by*128 + _r) * K + (kk) + lc8*8;               \
            size_t _br = (size_t)(bx*128 + _r) * K + (kk) + lc8*8;               \
            cpasync16(_b          + _o, Ah + _ar);                               \
            cpasync16(_b +  BUFB  + _o, Bh + _br);                               \
        }                                                                        \
        {                                                                        \
            uint32_t _o8 = l8r * SA8 + c8 * 16;                                  \
            size_t _a8 = (size_t)(by*128 + l8r) * K + (kk) + c8*16;              \
            size_t _b8 = (size_t)(bx*128 + l8r) * K + (kk) + c8*16;              \
            cpasync16(_b + 2*BUFB         + _o8, A8  + _a8);                     \
            cpasync16(_b + 2*BUFB + BUF8  + _o8, Bl8 + _b8);                     \
        }                                                                        \
        asm volatile("cp.async.commit_group;" ::: "memory");                     \
    } while (0)

    float acc[4][4][4];
    #pragma unroll
    for (int i = 0; i < 4; i++)
        #pragma unroll
        for (int j = 0; j < 4; j++)
            #pragma unroll
            for (int q = 0; q < 4; q++) acc[i][j][q] = 0.f;

    LD_STAGE(0, 0);

    for (int kt = 0; kt < nK; kt++) {
        asm volatile("cp.async.wait_group 0;" ::: "memory");
        __syncthreads();
        if (kt + 1 < nK) LD_STAGE((kt + 1) & 1, (kt + 1) * 32);

        const uint32_t st = sb0 + (kt & 1) * STGB;
        // fp8 correction product: one K=32 step per kt
        {
            uint32_t b8[4][2];
            #pragma unroll
            for (int nip = 0; nip < 2; nip++) {
                uint32_t ba = st + 2*BUFB + BUF8 + b8_off + nip * (16*SA8);
                ldmx4(b8[2*nip][0], b8[2*nip][1], b8[2*nip+1][0], b8[2*nip+1][1], ba);
            }
            #pragma unroll
            for (int mi = 0; mi < 4; mi++) {
                uint32_t aa = st + 2*BUFB + a8_off + mi * (16*SA8);
                uint32_t a0,a1,a2,a3;
                ldmx4(a0, a1, a2, a3, aa);
                #pragma unroll
                for (int ni = 0; ni < 4; ni++)
                    mma16832f8(acc[mi][ni], a0,a1,a2,a3, b8[ni][0], b8[ni][1]);
            }
        }
        // fp16 hi product: two K=16 steps
        #pragma unroll
        for (int ks = 0; ks < 2; ks++) {
            uint32_t bh[4][2];
            #pragma unroll
            for (int nip = 0; nip < 2; nip++) {
                uint32_t ba = st + BUFB + b_off + nip * (16*SAB) + ks * 32;
                ldmx4(bh[2*nip][0], bh[2*nip][1], bh[2*nip+1][0], bh[2*nip+1][1], ba);
            }
            #pragma unroll
            for (int mi = 0; mi < 4; mi++) {
                uint32_t aa = st + a_off + mi * (16*SAB) + ks * 32;
                uint32_t a0,a1,a2,a3;
                ldmx4(a0, a1, a2, a3, aa);
                #pragma unroll
                for (int ni = 0; ni < 4; ni++)
                    mma16816(acc[mi][ni], a0,a1,a2,a3, bh[ni][0], bh[ni][1]);
            }
        }
    }

    // epilogue
    const int gr = lane >> 2, gc = (lane & 3) * 2;
    const int row0 = by*128 + wm*64;
    const int col0 = bx*128 + wn*32;
    #pragma unroll
    for (int mi = 0; mi < 4; mi++)
        #pragma unroll
        for (int h2 = 0; h2 < 2; h2++) {
            int row = row0 + mi*16 + gr + h2*8;
            #pragma unroll
            for (int ni = 0; ni < 4; ni++) {
                int col = col0 + ni*8 + gc;
                size_t idx = (size_t)row * N + col;
                float v0 = acc[mi][ni][h2*2+0] + bias[col];
                float v1 = acc[mi][ni][h2*2+1] + bias[col+1];
                if (MODE == 0) {
                    v0 = gelu_exact(v0); v1 = gelu_exact(v1);
                    uint16_t q = (uint16_t)to_e4m3(v0*A8SCALE)
                               | ((uint16_t)to_e4m3(v1*A8SCALE) << 8);
                    *(uint16_t*)(C8 + idx) = q;
                } else {
                    float2 old = *(const float2*)(Cf + idx);
                    v0 += old.x; v1 += old.y;
                    if (MODE == 1) *(float2*)(Cf + idx) = make_float2(v0, v1);
                }
                *(__half2*)(Ch + idx) =
                    __halves2half2(__float2half_rn(v0), __float2half_rn(v1));
            }
        }
}

// ---------------- head (warp-per-token): logits via folded skW ---------------
__global__ void head_kernel(float* __restrict__ out) {
    int wi = threadIdx.x >> 5, lane = threadIdx.x & 31;
    int t = blockIdx.x * 4 + wi;
    float l0 = 0.f, l1 = 0.f, l2 = 0.f;
    #pragma unroll
    for (int l = 0; l < NLAYER; l++) {
        #pragma unroll
        for (int j = 0; j < 4; j++) {
            int d = (lane + j*32) * 4;
            size_t hb = (size_t)t*ND + d;
            __half2 p0 = *(const __half2*)(&d_hl4[l][hb]);
            __half2 p1 = *(const __half2*)(&d_hl4[l][hb + 2]);
            float vv[4] = { __half2float(p0.x), __half2float(p0.y),
                            __half2float(p1.x), __half2float(p1.y) };
            const float* wr = d_skW + (l*ND + d) * 3;
            #pragma unroll
            for (int i = 0; i < 4; i++) {
                l0 += vv[i]*wr[i*3+0]; l1 += vv[i]*wr[i*3+1]; l2 += vv[i]*wr[i*3+2];
            }
        }
    }
    l0 = warpReduceSum(l0); l1 = warpReduceSum(l1); l2 = warpReduceSum(l2);
    if (lane == 0) {
        l0 += d_cst[0]; l1 += d_cst[1]; l2 += d_cst[2];
        float m = fmaxf(l0, fmaxf(l1, l2));
        float e0 = expf(l0-m), e1 = expf(l1-m), e2 = expf(l2-m);
        float inv = 1.0f / (e0+e1+e2);
        out[t*3+0] = e0*inv; out[t*3+1] = e1*inv; out[t*3+2] = e2*inv;
    }
}

// ---------------- launcher ---------------------------------------------------
extern "C" void kernel_launch(void* const* d_in, const int* in_sizes, int n_in,
                              void* d_out, int out_size) {
    const float* x       = (const float*)d_in[0];
    const float* embed_w = (const float*)d_in[1];
    const float* embed_b = (const float*)d_in[2];
    const float* pe      = (const float*)d_in[3];
    const float* norm1_w = (const float*)d_in[4];
    const float* norm1_b = (const float*)d_in[5];
    const float* norm2_w = (const float*)d_in[6];
    const float* norm2_b = (const float*)d_in[7];
    const float* hy_proj = (const float*)d_in[8];
    const float* hy_coef = (const float*)d_in[9];
    const float* ffn_w1  = (const float*)d_in[10];
    const float* ffn_b1  = (const float*)d_in[11];
    const float* ffn_w2  = (const float*)d_in[12];
    const float* ffn_b2  = (const float*)d_in[13];
    const float* skip_w  = (const float*)d_in[14];
    const float* skip_b  = (const float*)d_in[15];
    const float* out_w   = (const float*)d_in[16];
    const float* out_b   = (const float*)d_in[17];
    float* out = (float*)d_out;

    float *hp;
    __half *thp, *ghp, *w1h, *w2h, *hl4;
    unsigned char *t8p, *g8p, *w1l8, *w2l8;
    cudaGetSymbolAddress((void**)&hp,  d_h);
    cudaGetSymbolAddress((void**)&thp, d_th);  cudaGetSymbolAddress((void**)&t8p, d_t8);
    cudaGetSymbolAddress((void**)&ghp, d_gh);  cudaGetSymbolAddress((void**)&g8p, d_g8);
    cudaGetSymbolAddress((void**)&hl4, d_hl4);
    cudaGetSymbolAddress((void**)&w1h, d_w1h); cudaGetSymbolAddress((void**)&w1l8, d_w1l8);
    cudaGetSymbolAddress((void**)&w2h, d_w2h); cudaGetSymbolAddress((void**)&w2l8, d_w2l8);

    cudaFuncSetAttribute(hgemm<0>, cudaFuncAttributeMaxDynamicSharedMemorySize, GSMEM);
    cudaFuncSetAttribute(hgemm<1>, cudaFuncAttributeMaxDynamicSharedMemorySize, GSMEM);
    cudaFuncSetAttribute(hgemm<2>, cudaFuncAttributeMaxDynamicSharedMemorySize, GSMEM);

    // weight prep (captured in graph)
    wsplitT<<<dim3(NF/32, ND/32, NLAYER), dim3(32,8)>>>(ffn_w1, w1h, w1l8, ND, NF);
    wsplitT<<<dim3(ND/32, NF/32, NLAYER), dim3(32,8)>>>(ffn_w2, w2h, w2l8, NF, ND);
    skw_prep<<<(NLAYER*ND*32)/256, 256>>>(skip_w, out_w);
    cst_prep<<<1, 96>>>(skip_b, out_w, out_b);

    embed_kernel<<<NT, 128>>>(x, embed_w, embed_b, pe);

    for (int l = 0; l < NLAYER; l++) {
        const float* coef = hy_coef + (size_t)l*NO*ND;
        ln1_proj_kernel<<<NT/4, 128>>>(norm1_w + l*ND, norm1_b + l*ND,
                                       hy_proj + (size_t)l*NO*ND);
        hyena_pass1<<<(NB*NCHUNK*ND)/256, 256>>>(coef);
        hyena_pass3<<<(NB*NCHUNK*ND)/256, 256>>>(coef);
        ln2_kernel<<<NT/4, 128>>>(norm2_w + l*ND, norm2_b + l*ND);

        // FFN GEMM1: g = gelu(tmp @ w1 + b1) -> fp16 + fp8
        hgemm<0><<<dim3(NF/128, NT/128), 256, GSMEM>>>(
            thp, t8p, w1h + (size_t)l*NF*ND, w1l8 + (size_t)l*NF*ND,
            ffn_b1 + (size_t)l*NF, NF, ND, nullptr, ghp, g8p);
        // FFN GEMM2: h = g @ w2 + b2 + h; store fp16 h_l for head
        if (l < NLAYER-1)
            hgemm<1><<<dim3(ND/128, NT/128), 256, GSMEM>>>(
                ghp, g8p, w2h + (size_t)l*ND*NF, w2l8 + (size_t)l*ND*NF,
                ffn_b2 + (size_t)l*ND, ND, NF, hp, hl4 + (size_t)l*NT*ND, nullptr);
        else   // last layer: d_h never read again -> skip the fp32 writeback
            hgemm<2><<<dim3(ND/128, NT/128), 256, GSMEM>>>(
                ghp, g8p, w2h + (size_t)l*ND*NF, w2l8 + (size_t)l*ND*NF,
                ffn_b2 + (size_t)l*ND, ND, NF, hp, hl4 + (size_t)l*NT*ND, nullptr);
    }

    head_kernel<<<NT/4, 128>>>(out);
}

// round 11
// speedup vs baseline: 1.2154x; 1.2154x over previous
#include <cuda_runtime.h>
#include <cuda_fp16.h>
#include <math.h>
#include <stdint.h>

// Problem constants
#define NB 4
#define NS 4096
#define ND 512
#define NO 4
#define NLAYER 4
#define NF 2048
#define NT (NB*NS)
#define NCHUNK 32
#define CLEN 128

// ---------------- scratch (static device globals) ----------------------------
__device__ __align__(256) float  d_h[(size_t)NT * ND];
__device__ __align__(256) float4 d_proj[NT];
__device__ __align__(256) float4 d_end[NB * NCHUNK * ND];
// fp16 activation buffers
__device__ __align__(256) __half d_th[(size_t)NT*ND];
__device__ __align__(256) __half d_gh[(size_t)NT*NF];
__device__ __align__(256) __half d_hl4[NLAYER][(size_t)NT*ND];  // per-layer h (fp16)
// transposed+split weights: [N,K] K-major, hi/lo
__device__ __align__(256) __half d_w1h[(size_t)NLAYER*NF*ND], d_w1l[(size_t)NLAYER*NF*ND];
__device__ __align__(256) __half d_w2h[(size_t)NLAYER*ND*NF], d_w2l[(size_t)NLAYER*ND*NF];
// folded head weights
__device__ __align__(256) float d_skW[NLAYER*ND*3];
__device__ __align__(256) float d_cst[3];

// ---------------- helpers ----------------------------------------------------
__device__ __forceinline__ uint32_t smem_u32(const void* p) {
    uint32_t a;
    asm("{ .reg .u64 t; cvta.to.shared.u64 t, %1; cvt.u32.u64 %0, t; }" : "=r"(a) : "l"(p));
    return a;
}
__device__ __forceinline__ void cpasync16(uint32_t s, const void* g) {
    asm volatile("cp.async.cg.shared.global [%0], [%1], 16;" :: "r"(s), "l"(g));
}
__device__ __forceinline__ void ldmx4(uint32_t& r0, uint32_t& r1, uint32_t& r2,
                                      uint32_t& r3, uint32_t addr) {
    asm volatile("ldmatrix.sync.aligned.m8n8.x4.shared.b16 {%0,%1,%2,%3}, [%4];"
        : "=r"(r0), "=r"(r1), "=r"(r2), "=r"(r3) : "r"(addr));
}
__device__ __forceinline__ void split2h(float v, __half& h, __half& l) {
    h = __float2half_rn(v);
    l = __float2half_rn(v - __half2float(h));
}
__device__ __forceinline__ float gelu_exact(float x) {
    return 0.5f * x * (1.0f + erff(x * 0.70710678118654752440f));
}
__device__ __forceinline__ float warpReduceSum(float v) {
    #pragma unroll
    for (int o = 16; o > 0; o >>= 1) v += __shfl_xor_sync(0xffffffffu, v, o);
    return v;
}
__device__ __forceinline__ void mma16816(float* c, uint32_t a0, uint32_t a1,
                                         uint32_t a2, uint32_t a3,
                                         uint32_t b0, uint32_t b1) {
    asm volatile("mma.sync.aligned.m16n8k16.row.col.f32.f16.f16.f32 "
        "{%0,%1,%2,%3}, {%4,%5,%6,%7}, {%8,%9}, {%0,%1,%2,%3};"
        : "+f"(c[0]), "+f"(c[1]), "+f"(c[2]), "+f"(c[3])
        : "r"(a0), "r"(a1), "r"(a2), "r"(a3), "r"(b0), "r"(b1));
}

// ---------------- weight transpose + split (batched over layers) -------------
__global__ void wsplitT(const float* __restrict__ w, __half* __restrict__ hi,
                        __half* __restrict__ lo, int K, int N) {
    __shared__ float t[32][33];
    size_t loff = (size_t)blockIdx.z * K * N;
    int n0 = blockIdx.x * 32, k0 = blockIdx.y * 32;
    int tx = threadIdx.x, ty = threadIdx.y;   // (32,8)
    #pragma unroll
    for (int j = 0; j < 4; j++) {
        int r = ty * 4 + j;
        t[r][tx] = w[loff + (size_t)(k0 + r) * N + n0 + tx];
    }
    __syncthreads();
    #pragma unroll
    for (int j = 0; j < 4; j++) {
        int r = ty * 4 + j;
        float v = t[tx][r];
        __half h, l; split2h(v, h, l);
        size_t oi = loff + (size_t)(n0 + r) * K + k0 + tx;
        hi[oi] = h; lo[oi] = l;
    }
}

// ---------------- fold skip weights: skW = skip_w @ out_w (warp per (l,d)) ---
__global__ void skw_prep(const float* __restrict__ skip_w, const float* __restrict__ ow) {
    int w = (blockIdx.x * blockDim.x + threadIdx.x) >> 5;
    int lane = threadIdx.x & 31;
    int l = w >> 9, d = w & (ND-1);
    const float* wr = skip_w + ((size_t)l * ND + d) * ND;
    float s0 = 0.f, s1 = 0.f, s2 = 0.f;
    for (int n = lane; n < ND; n += 32) {
        float v = wr[n];
        const float* o = ow + n * 3;
        s0 += v * o[0]; s1 += v * o[1]; s2 += v * o[2];
    }
    s0 = warpReduceSum(s0); s1 = warpReduceSum(s1); s2 = warpReduceSum(s2);
    if (lane == 0) {
        float* dst = d_skW + (l * ND + d) * 3;
        dst[0] = s0; dst[1] = s1; dst[2] = s2;
    }
}
// cst[j] = ob[j] + sum_{l,n} skip_b[l,n]*ow[n,j]; 24 warps = 8 chunks x 3 j
__global__ void cst_prep(const float* __restrict__ skip_b, const float* __restrict__ ow,
                         const float* __restrict__ ob) {
    __shared__ float part[3][8];
    int wid = threadIdx.x >> 5, lane = threadIdx.x & 31;
    int j = wid % 3, chunk = wid / 3;          // 768 threads = 24 warps
    float s = 0.f;
    for (int i = lane; i < 256; i += 32) {
        int ln = chunk * 256 + i;
        s += skip_b[ln] * ow[(ln & (ND-1)) * 3 + j];
    }
    s = warpReduceSum(s);
    if (lane == 0) part[j][chunk] = s;
    __syncthreads();
    if (threadIdx.x < 3) {
        float tot = ob[threadIdx.x];
        #pragma unroll
        for (int c = 0; c < 8; c++) tot += part[threadIdx.x][c];
        d_cst[threadIdx.x] = tot;
    }
}

// ---------------- embed ------------------------------------------------------
__global__ void embed_kernel(const float* __restrict__ x, const float* __restrict__ ew,
                             const float* __restrict__ eb, const float* __restrict__ pe) {
    int t = blockIdx.x, tid = threadIdx.x;
    int s = t & (NS - 1);
    float x0 = x[t*4+0], x1 = x[t*4+1], x2 = x[t*4+2], x3 = x[t*4+3];
    float4 e0 = ((const float4*)(ew        ))[tid];
    float4 e1 = ((const float4*)(ew +   ND))[tid];
    float4 e2 = ((const float4*)(ew + 2*ND))[tid];
    float4 e3 = ((const float4*)(ew + 3*ND))[tid];
    float4 bb = ((const float4*)eb)[tid];
    float4 pp = ((const float4*)(pe + (size_t)s*ND))[tid];
    float4 r;
    r.x = x0*e0.x + x1*e1.x + x2*e2.x + x3*e3.x + bb.x + pp.x;
    r.y = x0*e0.y + x1*e1.y + x2*e2.y + x3*e3.y + bb.y + pp.y;
    r.z = x0*e0.z + x1*e1.z + x2*e2.z + x3*e3.z + bb.z + pp.z;
    r.w = x0*e0.w + x1*e1.w + x2*e2.w + x3*e3.w + bb.w + pp.w;
    ((float4*)(d_h + (size_t)t*ND))[tid] = r;
}

// ---------------- fused LN1 + hyena projection (warp-per-token) --------------
__global__ void ln1_proj_kernel(const float* __restrict__ w, const float* __restrict__ bta,
                                const float* __restrict__ P) {
    int wi = threadIdx.x >> 5, lane = threadIdx.x & 31;
    int t = blockIdx.x * 4 + wi;
    const float4* hrow = (const float4*)(d_h + (size_t)t * ND);
    float4 v[4];
    float sum = 0.f;
    #pragma unroll
    for (int j = 0; j < 4; j++) {
        v[j] = hrow[lane + j*32];
        sum += v[j].x + v[j].y + v[j].z + v[j].w;
    }
    float mu = warpReduceSum(sum) * (1.0f/ND);
    float sq = 0.f;
    #pragma unroll
    for (int j = 0; j < 4; j++) {
        float a0=v[j].x-mu, a1=v[j].y-mu, a2=v[j].z-mu, a3=v[j].w-mu;
        sq += a0*a0 + a1*a1 + a2*a2 + a3*a3;
    }
    float rs = rsqrtf(warpReduceSum(sq) * (1.0f/ND) + 1e-5f);
    float p0=0.f, p1=0.f, p2=0.f, p3=0.f;
    #pragma unroll
    for (int j = 0; j < 4; j++) {
        int f4 = lane + j*32;
        float4 wv = ((const float4*)w)[f4];
        float4 bv = ((const float4*)bta)[f4];
        float n0=(v[j].x-mu)*rs*wv.x+bv.x, n1=(v[j].y-mu)*rs*wv.y+bv.y;
        float n2=(v[j].z-mu)*rs*wv.z+bv.z, n3=(v[j].w-mu)*rs*wv.w+bv.w;
        float4 q0 = ((const float4*)(P       ))[f4];
        float4 q1 = ((const float4*)(P +   ND))[f4];
        float4 q2 = ((const float4*)(P + 2*ND))[f4];
        float4 q3 = ((const float4*)(P + 3*ND))[f4];
        p0 += n0*q0.x + n1*q0.y + n2*q0.z + n3*q0.w;
        p1 += n0*q1.x + n1*q1.y + n2*q1.z + n3*q1.w;
        p2 += n0*q2.x + n1*q2.y + n2*q2.z + n3*q2.w;
        p3 += n0*q3.x + n1*q3.y + n2*q3.z + n3*q3.w;
    }
    p0 = warpReduceSum(p0); p1 = warpReduceSum(p1);
    p2 = warpReduceSum(p2); p3 = warpReduceSum(p3);
    if (lane == 0) d_proj[t] = make_float4(p0, p1, p2, p3);
}

// ---------------- hyena scan -------------------------------------------------
__global__ void hyena_pass1(const float* __restrict__ coef) {
    int tid = blockIdx.x * blockDim.x + threadIdx.x;
    int d = tid & (ND-1);
    int k = (tid >> 9) & (NCHUNK-1);
    int b = tid >> 14;
    float l0 = expf(coef[0*ND+d]), l1 = expf(coef[1*ND+d]);
    float l2 = expf(coef[2*ND+d]), l3 = expf(coef[3*ND+d]);
    float c0=0.f, c1=0.f, c2=0.f, c3=0.f;
    int base = b*NS + k*CLEN;
    #pragma unroll 4
    for (int j = 0; j < CLEN; j++) {
        float4 p = d_proj[base + j];
        c0 = c0*l0 + p.x; c1 = c1*l1 + p.y;
        c2 = c2*l2 + p.z; c3 = c3*l3 + p.w;
    }
    d_end[(b*NCHUNK + k)*ND + d] = make_float4(c0, c1, c2, c3);
}

// pass3 with inlined chunk-combine: carry-in from d_end prefix
__global__ void hyena_pass3(const float* __restrict__ coef) {
    int tid = blockIdx.x * blockDim.x + threadIdx.x;
    int d = tid & (ND-1);
    int k = (tid >> 9) & (NCHUNK-1);
    int b = tid >> 14;
    float l0 = expf(coef[0*ND+d]), l1 = expf(coef[1*ND+d]);
    float l2 = expf(coef[2*ND+d]), l3 = expf(coef[3*ND+d]);
    float L0 = expf(coef[0*ND+d]*(float)CLEN), L1 = expf(coef[1*ND+d]*(float)CLEN);
    float L2 = expf(coef[2*ND+d]*(float)CLEN), L3 = expf(coef[3*ND+d]*(float)CLEN);
    float4 c = make_float4(0.f, 0.f, 0.f, 0.f);
    for (int j = 0; j < k; j++) {
        float4 e = d_end[(b*NCHUNK + j)*ND + d];
        c.x = c.x*L0 + e.x; c.y = c.y*L1 + e.y;
        c.z = c.z*L2 + e.z; c.w = c.w*L3 + e.w;
    }
    int base = b*NS + k*CLEN;
    #pragma unroll 4
    for (int j = 0; j < CLEN; j++) {
        float4 p = d_proj[base + j];
        c.x = c.x*l0 + p.x; c.y = c.y*l1 + p.y;
        c.z = c.z*l2 + p.z; c.w = c.w*l3 + p.w;
        size_t idx = (size_t)(base + j)*ND + d;
        d_h[idx] += c.x + c.y + c.z + c.w;
    }
}

// ---------------- LN2 (warp-per-token): h -> fp16 d_th -----------------------
__global__ void ln2_kernel(const float* __restrict__ w, const float* __restrict__ bta) {
    int wi = threadIdx.x >> 5, lane = threadIdx.x & 31;
    int t = blockIdx.x * 4 + wi;
    const float4* hrow = (const float4*)(d_h + (size_t)t * ND);
    float4 v[4];
    float sum = 0.f;
    #pragma unroll
    for (int j = 0; j < 4; j++) {
        v[j] = hrow[lane + j*32];
        sum += v[j].x + v[j].y + v[j].z + v[j].w;
    }
    float mu = warpReduceSum(sum) * (1.0f/ND);
    float sq = 0.f;
    #pragma unroll
    for (int j = 0; j < 4; j++) {
        float a0=v[j].x-mu, a1=v[j].y-mu, a2=v[j].z-mu, a3=v[j].w-mu;
        sq += a0*a0 + a1*a1 + a2*a2 + a3*a3;
    }
    float rs = rsqrtf(warpReduceSum(sq) * (1.0f/ND) + 1e-5f);
    size_t trow = (size_t)t * ND;
    #pragma unroll
    for (int j = 0; j < 4; j++) {
        int f4 = lane + j*32;
        float4 wv = ((const float4*)w)[f4];
        float4 bv = ((const float4*)bta)[f4];
        float r0=(v[j].x-mu)*rs*wv.x+bv.x, r1=(v[j].y-mu)*rs*wv.y+bv.y;
        float r2=(v[j].z-mu)*rs*wv.z+bv.z, r3=(v[j].w-mu)*rs*wv.w+bv.w;
        *(__half2*)(d_th + trow + f4*4    ) =
            __halves2half2(__float2half_rn(r0), __float2half_rn(r1));
        *(__half2*)(d_th + trow + f4*4 + 2) =
            __halves2half2(__float2half_rn(r2), __float2half_rn(r3));
    }
}

// ---------------- 2-product HMMA GEMM (R9 mainloop) --------------------------
// MODE 0: gelu(acc+bias) -> Ch
// MODE 1: r = acc+bias+Cf; Cf=r; Ch=fp16(r)
// MODE 2: r = acc+bias+Cf; (no Cf write) Ch=fp16(r)
#define SAB   80
#define BUFB  (128*SAB)
#define STGB  (3*BUFB)
#define GSMEM (2*STGB)

template<int MODE>
__global__ void __launch_bounds__(256, 2)
hgemm(const __half* __restrict__ Ah,
      const __half* __restrict__ Bh, const __half* __restrict__ Bl,
      const float* __restrict__ bias, int N, int K,
      float* __restrict__ Cf, __half* __restrict__ Ch)
{
    extern __shared__ char smem[];
    const int tid = threadIdx.x, lane = tid & 31, w = tid >> 5;
    const int wm = w >> 2, wn = w & 3;
    const int bx = blockIdx.x, by = blockIdx.y;
    const int nK = K >> 5;
    const uint32_t sb0 = smem_u32(smem);

    const uint32_t a_off = (uint32_t)(wm*64 + (lane & 7) + ((lane >> 3) & 1) * 8) * SAB
                         + ((lane >> 4) & 1) * 16;
    const uint32_t b_off = (uint32_t)(wn*32 + (lane & 7) + ((lane >> 4) & 1) * 8) * SAB
                         + ((lane >> 3) & 1) * 16;

    const int lr = tid >> 2, lc8 = tid & 3;
    #define LD_STAGE(s, kk) do {                                                 \
        uint32_t _b = sb0 + (s) * STGB;                                          \
        _Pragma("unroll")                                                        \
        for (int _i = 0; _i < 2; _i++) {                                         \
            int _r = lr + _i * 64;                                               \
            uint32_t _o = _r * SAB + lc8 * 16;                                   \
            size_t _ar = (size_t)(by*128 + _r) * K + (kk) + lc8*8;               \
            size_t _br = (size_t)(bx*128 + _r) * K + (kk) + lc8*8;               \
            cpasync16(_b           + _o, Ah + _ar);                              \
            cpasync16(_b +   BUFB  + _o, Bh + _br);                              \
            cpasync16(_b + 2*BUFB  + _o, Bl + _br);                              \
        }                                                                        \
        asm volatile("cp.async.commit_group;" ::: "memory");                     \
    } while (0)

    float acc[4][4][4];
    #pragma unroll
    for (int i = 0; i < 4; i++)
        #pragma unroll
        for (int j = 0; j < 4; j++)
            #pragma unroll
            for (int q = 0; q < 4; q++) acc[i][j][q] = 0.f;

    LD_STAGE(0, 0);

    for (int kt = 0; kt < nK; kt++) {
        asm volatile("cp.async.wait_group 0;" ::: "memory");
        __syncthreads();
        if (kt + 1 < nK) LD_STAGE((kt + 1) & 1, (kt + 1) * 32);

        const uint32_t st = sb0 + (kt & 1) * STGB;
        #pragma unroll
        for (int ks = 0; ks < 2; ks++) {
            uint32_t bh[4][2], bl[4][2];
            #pragma unroll
            for (int nip = 0; nip < 2; nip++) {
                uint32_t ba = st + BUFB + b_off + nip * (16*SAB) + ks * 32;
                ldmx4(bh[2*nip][0], bh[2*nip][1], bh[2*nip+1][0], bh[2*nip+1][1], ba);
                ldmx4(bl[2*nip][0], bl[2*nip][1], bl[2*nip+1][0], bl[2*nip+1][1], ba + BUFB);
            }
            #pragma unroll
            for (int mi = 0; mi < 4; mi++) {
                uint32_t aa = st + a_off + mi * (16*SAB) + ks * 32;
                uint32_t a0,a1,a2,a3;
                ldmx4(a0, a1, a2, a3, aa);
                #pragma unroll
                for (int ni = 0; ni < 4; ni++) {
                    mma16816(acc[mi][ni], a0,a1,a2,a3, bh[ni][0], bh[ni][1]);
                    mma16816(acc[mi][ni], a0,a1,a2,a3, bl[ni][0], bl[ni][1]);
                }
            }
        }
    }

    // epilogue
    const int gr = lane >> 2, gc = (lane & 3) * 2;
    const int row0 = by*128 + wm*64;
    const int col0 = bx*128 + wn*32;
    #pragma unroll
    for (int mi = 0; mi < 4; mi++)
        #pragma unroll
        for (int h2 = 0; h2 < 2; h2++) {
            int row = row0 + mi*16 + gr + h2*8;
            #pragma unroll
            for (int ni = 0; ni < 4; ni++) {
                int col = col0 + ni*8 + gc;
                size_t idx = (size_t)row * N + col;
                float v0 = acc[mi][ni][h2*2+0] + bias[col];
                float v1 = acc[mi][ni][h2*2+1] + bias[col+1];
                if (MODE == 0) {
                    v0 = gelu_exact(v0); v1 = gelu_exact(v1);
                } else {
                    float2 old = *(const float2*)(Cf + idx);
                    v0 += old.x; v1 += old.y;
                    if (MODE == 1) *(float2*)(Cf + idx) = make_float2(v0, v1);
                }
                *(__half2*)(Ch + idx) =
                    __halves2half2(__float2half_rn(v0), __float2half_rn(v1));
            }
        }
}

// ---------------- head (warp-per-token): logits via folded skW ---------------
__global__ void head_kernel(float* __restrict__ out) {
    int wi = threadIdx.x >> 5, lane = threadIdx.x & 31;
    int t = blockIdx.x * 4 + wi;
    float l0 = 0.f, l1 = 0.f, l2 = 0.f;
    #pragma unroll
    for (int l = 0; l < NLAYER; l++) {
        #pragma unroll
        for (int j = 0; j < 4; j++) {
            int d = (lane + j*32) * 4;
            size_t hb = (size_t)t*ND + d;
            __half2 p0 = *(const __half2*)(&d_hl4[l][hb]);
            __half2 p1 = *(const __half2*)(&d_hl4[l][hb + 2]);
            float vv[4] = { __half2float(p0.x), __half2float(p0.y),
                            __half2float(p1.x), __half2float(p1.y) };
            const float* wr = d_skW + (l*ND + d) * 3;
            #pragma unroll
            for (int i = 0; i < 4; i++) {
                l0 += vv[i]*wr[i*3+0]; l1 += vv[i]*wr[i*3+1]; l2 += vv[i]*wr[i*3+2];
            }
        }
    }
    l0 = warpReduceSum(l0); l1 = warpReduceSum(l1); l2 = warpReduceSum(l2);
    if (lane == 0) {
        l0 += d_cst[0]; l1 += d_cst[1]; l2 += d_cst[2];
        float m = fmaxf(l0, fmaxf(l1, l2));
        float e0 = expf(l0-m), e1 = expf(l1-m), e2 = expf(l2-m);
        float inv = 1.0f / (e0+e1+e2);
        out[t*3+0] = e0*inv; out[t*3+1] = e1*inv; out[t*3+2] = e2*inv;
    }
}

// ---------------- launcher ---------------------------------------------------
extern "C" void kernel_launch(void* const* d_in, const int* in_sizes, int n_in,
                              void* d_out, int out_size) {
    const float* x       = (const float*)d_in[0];
    const float* embed_w = (const float*)d_in[1];
    const float* embed_b = (const float*)d_in[2];
    const float* pe      = (const float*)d_in[3];
    const float* norm1_w = (const float*)d_in[4];
    const float* norm1_b = (const float*)d_in[5];
    const float* norm2_w = (const float*)d_in[6];
    const float* norm2_b = (const float*)d_in[7];
    const float* hy_proj = (const float*)d_in[8];
    const float* hy_coef = (const float*)d_in[9];
    const float* ffn_w1  = (const float*)d_in[10];
    const float* ffn_b1  = (const float*)d_in[11];
    const float* ffn_w2  = (const float*)d_in[12];
    const float* ffn_b2  = (const float*)d_in[13];
    const float* skip_w  = (const float*)d_in[14];
    const float* skip_b  = (const float*)d_in[15];
    const float* out_w   = (const float*)d_in[16];
    const float* out_b   = (const float*)d_in[17];
    float* out = (float*)d_out;

    float *hp;
    __half *thp, *ghp, *w1h, *w1l, *w2h, *w2l, *hl4;
    cudaGetSymbolAddress((void**)&hp,  d_h);
    cudaGetSymbolAddress((void**)&thp, d_th);
    cudaGetSymbolAddress((void**)&ghp, d_gh);
    cudaGetSymbolAddress((void**)&hl4, d_hl4);
    cudaGetSymbolAddress((void**)&w1h, d_w1h); cudaGetSymbolAddress((void**)&w1l, d_w1l);
    cudaGetSymbolAddress((void**)&w2h, d_w2h); cudaGetSymbolAddress((void**)&w2l, d_w2l);

    cudaFuncSetAttribute(hgemm<0>, cudaFuncAttributeMaxDynamicSharedMemorySize, GSMEM);
    cudaFuncSetAttribute(hgemm<1>, cudaFuncAttributeMaxDynamicSharedMemorySize, GSMEM);
    cudaFuncSetAttribute(hgemm<2>, cudaFuncAttributeMaxDynamicSharedMemorySize, GSMEM);

    // weight prep (captured in graph)
    wsplitT<<<dim3(NF/32, ND/32, NLAYER), dim3(32,8)>>>(ffn_w1, w1h, w1l, ND, NF);
    wsplitT<<<dim3(ND/32, NF/32, NLAYER), dim3(32,8)>>>(ffn_w2, w2h, w2l, NF, ND);
    skw_prep<<<(NLAYER*ND*32)/256, 256>>>(skip_w, out_w);
    cst_prep<<<1, 768>>>(skip_b, out_w, out_b);

    embed_kernel<<<NT, 128>>>(x, embed_w, embed_b, pe);

    for (int l = 0; l < NLAYER; l++) {
        const float* coef = hy_coef + (size_t)l*NO*ND;
        ln1_proj_kernel<<<NT/4, 128>>>(norm1_w + l*ND, norm1_b + l*ND,
                                       hy_proj + (size_t)l*NO*ND);
        hyena_pass1<<<(NB*NCHUNK*ND)/256, 256>>>(coef);
        hyena_pass3<<<(NB*NCHUNK*ND)/256, 256>>>(coef);
        ln2_kernel<<<NT/4, 128>>>(norm2_w + l*ND, norm2_b + l*ND);

        // FFN GEMM1: g = gelu(tmp @ w1 + b1)
        hgemm<0><<<dim3(NF/128, NT/128), 256, GSMEM>>>(
            thp, w1h + (size_t)l*NF*ND, w1l + (size_t)l*NF*ND,
            ffn_b1 + (size_t)l*NF, NF, ND, nullptr, ghp);
        // FFN GEMM2: h = g @ w2 + b2 + h; store fp16 h_l for head
        if (l < NLAYER-1)
            hgemm<1><<<dim3(ND/128, NT/128), 256, GSMEM>>>(
                ghp, w2h + (size_t)l*ND*NF, w2l + (size_t)l*ND*NF,
                ffn_b2 + (size_t)l*ND, ND, NF, hp, hl4 + (size_t)l*NT*ND);
        else   // last layer: d_h never read again -> skip the fp32 writeback
            hgemm<2><<<dim3(ND/128, NT/128), 256, GSMEM>>>(
                ghp, w2h + (size_t)l*ND*NF, w2l + (size_t)l*ND*NF,
                ffn_b2 + (size_t)l*ND, ND, NF, hp, hl4 + (size_t)l*NT*ND);
    }

    head_kernel<<<NT/4, 128>>>(out);
}

// round 12
// speedup vs baseline: 1.2200x; 1.0038x over previous
#include <cuda_runtime.h>
#include <cuda_fp16.h>
#include <math.h>
#include <stdint.h>

// Problem constants
#define NB 4
#define NS 4096
#define ND 512
#define NO 4
#define NLAYER 4
#define NF 2048
#define NT (NB*NS)
#define NCHUNK 32
#define CLEN 128

// ---------------- scratch (static device globals) ----------------------------
__device__ __align__(256) float  d_h[(size_t)NT * ND];
__device__ __align__(256) float4 d_proj[NT];
__device__ __align__(256) float4 d_end[NB * NCHUNK * ND];
// fp16 activation buffers
__device__ __align__(256) __half d_th[(size_t)NT*ND];
__device__ __align__(256) __half d_gh[(size_t)NT*NF];
__device__ __align__(256) __half d_hl4[NLAYER][(size_t)NT*ND];  // per-layer h (fp16)
// transposed+split weights: [N,K] K-major, hi/lo
__device__ __align__(256) __half d_w1h[(size_t)NLAYER*NF*ND], d_w1l[(size_t)NLAYER*NF*ND];
__device__ __align__(256) __half d_w2h[(size_t)NLAYER*ND*NF], d_w2l[(size_t)NLAYER*ND*NF];
// folded head weights
__device__ __align__(256) float d_skW[NLAYER*ND*3];
__device__ __align__(256) float d_cst[3];

// ---------------- helpers ----------------------------------------------------
__device__ __forceinline__ uint32_t smem_u32(const void* p) {
    uint32_t a;
    asm("{ .reg .u64 t; cvta.to.shared.u64 t, %1; cvt.u32.u64 %0, t; }" : "=r"(a) : "l"(p));
    return a;
}
__device__ __forceinline__ void cpasync16(uint32_t s, const void* g) {
    asm volatile("cp.async.cg.shared.global [%0], [%1], 16;" :: "r"(s), "l"(g));
}
__device__ __forceinline__ void ldmx4(uint32_t& r0, uint32_t& r1, uint32_t& r2,
                                      uint32_t& r3, uint32_t addr) {
    asm volatile("ldmatrix.sync.aligned.m8n8.x4.shared.b16 {%0,%1,%2,%3}, [%4];"
        : "=r"(r0), "=r"(r1), "=r"(r2), "=r"(r3) : "r"(addr));
}
__device__ __forceinline__ void split2h(float v, __half& h, __half& l) {
    h = __float2half_rn(v);
    l = __float2half_rn(v - __half2float(h));
}
__device__ __forceinline__ float gelu_exact(float x) {
    return 0.5f * x * (1.0f + erff(x * 0.70710678118654752440f));
}
__device__ __forceinline__ float warpReduceSum(float v) {
    #pragma unroll
    for (int o = 16; o > 0; o >>= 1) v += __shfl_xor_sync(0xffffffffu, v, o);
    return v;
}
__device__ __forceinline__ void mma16816(float* c, uint32_t a0, uint32_t a1,
                                         uint32_t a2, uint32_t a3,
                                         uint32_t b0, uint32_t b1) {
    asm volatile("mma.sync.aligned.m16n8k16.row.col.f32.f16.f16.f32 "
        "{%0,%1,%2,%3}, {%4,%5,%6,%7}, {%8,%9}, {%0,%1,%2,%3};"
        : "+f"(c[0]), "+f"(c[1]), "+f"(c[2]), "+f"(c[3])
        : "r"(a0), "r"(a1), "r"(a2), "r"(a3), "r"(b0), "r"(b1));
}

// ---------------- weight transpose + split (batched over layers) -------------
__global__ void wsplitT(const float* __restrict__ w, __half* __restrict__ hi,
                        __half* __restrict__ lo, int K, int N) {
    __shared__ float t[32][33];
    size_t loff = (size_t)blockIdx.z * K * N;
    int n0 = blockIdx.x * 32, k0 = blockIdx.y * 32;
    int tx = threadIdx.x, ty = threadIdx.y;   // (32,8)
    #pragma unroll
    for (int j = 0; j < 4; j++) {
        int r = ty * 4 + j;
        t[r][tx] = w[loff + (size_t)(k0 + r) * N + n0 + tx];
    }
    __syncthreads();
    #pragma unroll
    for (int j = 0; j < 4; j++) {
        int r = ty * 4 + j;
        float v = t[tx][r];
        __half h, l; split2h(v, h, l);
        size_t oi = loff + (size_t)(n0 + r) * K + k0 + tx;
        hi[oi] = h; lo[oi] = l;
    }
}

// ---------------- fold skip weights + constant (single launch) ---------------
// blocks 0..255: warp per (l,d) -> skW.  block 256: d_cst.
__global__ void skw_prep(const float* __restrict__ skip_w, const float* __restrict__ skip_b,
                         const float* __restrict__ ow, const float* __restrict__ ob) {
    int lane = threadIdx.x & 31;
    if (blockIdx.x < 256) {
        int w = (blockIdx.x * blockDim.x + threadIdx.x) >> 5;
        int l = w >> 9, d = w & (ND-1);
        const float* wr = skip_w + ((size_t)l * ND + d) * ND;
        float s0 = 0.f, s1 = 0.f, s2 = 0.f;
        for (int n = lane; n < ND; n += 32) {
            float v = wr[n];
            const float* o = ow + n * 3;
            s0 += v * o[0]; s1 += v * o[1]; s2 += v * o[2];
        }
        s0 = warpReduceSum(s0); s1 = warpReduceSum(s1); s2 = warpReduceSum(s2);
        if (lane == 0) {
            float* dst = d_skW + (l * ND + d) * 3;
            dst[0] = s0; dst[1] = s1; dst[2] = s2;
        }
    } else {
        __shared__ float part[3][2];
        int wid = threadIdx.x >> 5;          // 8 warps, use 6
        if (wid < 6) {
            int j = wid % 3, chunk = wid / 3;
            float s = 0.f;
            for (int i = lane; i < 1024; i += 32) {
                int ln = chunk * 1024 + i;
                s += skip_b[ln] * ow[(ln & (ND-1)) * 3 + j];
            }
            s = warpReduceSum(s);
            if (lane == 0) part[j][chunk] = s;
        }
        __syncthreads();
        if (threadIdx.x < 3)
            d_cst[threadIdx.x] = ob[threadIdx.x] + part[threadIdx.x][0] + part[threadIdx.x][1];
    }
}

// ---------------- embed (block per s; pe/ew read once, 4 batch tokens) -------
__global__ void embed_kernel(const float* __restrict__ x, const float* __restrict__ ew,
                             const float* __restrict__ eb, const float* __restrict__ pe) {
    int s = blockIdx.x, tid = threadIdx.x;   // 4096 blocks x 128 threads
    float4 e0 = ((const float4*)(ew        ))[tid];
    float4 e1 = ((const float4*)(ew +   ND))[tid];
    float4 e2 = ((const float4*)(ew + 2*ND))[tid];
    float4 e3 = ((const float4*)(ew + 3*ND))[tid];
    float4 bb = ((const float4*)eb)[tid];
    float4 pp = ((const float4*)(pe + (size_t)s*ND))[tid];
    float bx = bb.x + pp.x, by = bb.y + pp.y, bz = bb.z + pp.z, bw = bb.w + pp.w;
    #pragma unroll
    for (int b = 0; b < NB; b++) {
        int t = b*NS + s;
        float x0 = x[t*4+0], x1 = x[t*4+1], x2 = x[t*4+2], x3 = x[t*4+3];
        float4 r;
        r.x = x0*e0.x + x1*e1.x + x2*e2.x + x3*e3.x + bx;
        r.y = x0*e0.y + x1*e1.y + x2*e2.y + x3*e3.y + by;
        r.z = x0*e0.z + x1*e1.z + x2*e2.z + x3*e3.z + bz;
        r.w = x0*e0.w + x1*e1.w + x2*e2.w + x3*e3.w + bw;
        ((float4*)(d_h + (size_t)t*ND))[tid] = r;
    }
}

// ---------------- fused LN1 + hyena projection (warp-per-token) --------------
__global__ void ln1_proj_kernel(const float* __restrict__ w, const float* __restrict__ bta,
                                const float* __restrict__ P) {
    int wi = threadIdx.x >> 5, lane = threadIdx.x & 31;
    int t = blockIdx.x * 4 + wi;
    const float4* hrow = (const float4*)(d_h + (size_t)t * ND);
    float4 v[4];
    float sum = 0.f;
    #pragma unroll
    for (int j = 0; j < 4; j++) {
        v[j] = hrow[lane + j*32];
        sum += v[j].x + v[j].y + v[j].z + v[j].w;
    }
    float mu = warpReduceSum(sum) * (1.0f/ND);
    float sq = 0.f;
    #pragma unroll
    for (int j = 0; j < 4; j++) {
        float a0=v[j].x-mu, a1=v[j].y-mu, a2=v[j].z-mu, a3=v[j].w-mu;
        sq += a0*a0 + a1*a1 + a2*a2 + a3*a3;
    }
    float rs = rsqrtf(warpReduceSum(sq) * (1.0f/ND) + 1e-5f);
    float p0=0.f, p1=0.f, p2=0.f, p3=0.f;
    #pragma unroll
    for (int j = 0; j < 4; j++) {
        int f4 = lane + j*32;
        float4 wv = ((const float4*)w)[f4];
        float4 bv = ((const float4*)bta)[f4];
        float n0=(v[j].x-mu)*rs*wv.x+bv.x, n1=(v[j].y-mu)*rs*wv.y+bv.y;
        float n2=(v[j].z-mu)*rs*wv.z+bv.z, n3=(v[j].w-mu)*rs*wv.w+bv.w;
        float4 q0 = ((const float4*)(P       ))[f4];
        float4 q1 = ((const float4*)(P +   ND))[f4];
        float4 q2 = ((const float4*)(P + 2*ND))[f4];
        float4 q3 = ((const float4*)(P + 3*ND))[f4];
        p0 += n0*q0.x + n1*q0.y + n2*q0.z + n3*q0.w;
        p1 += n0*q1.x + n1*q1.y + n2*q1.z + n3*q1.w;
        p2 += n0*q2.x + n1*q2.y + n2*q2.z + n3*q2.w;
        p3 += n0*q3.x + n1*q3.y + n2*q3.z + n3*q3.w;
    }
    p0 = warpReduceSum(p0); p1 = warpReduceSum(p1);
    p2 = warpReduceSum(p2); p3 = warpReduceSum(p3);
    if (lane == 0) d_proj[t] = make_float4(p0, p1, p2, p3);
}

// ---------------- hyena scan -------------------------------------------------
__global__ void hyena_pass1(const float* __restrict__ coef) {
    int tid = blockIdx.x * blockDim.x + threadIdx.x;
    int d = tid & (ND-1);
    int k = (tid >> 9) & (NCHUNK-1);
    int b = tid >> 14;
    float l0 = expf(coef[0*ND+d]), l1 = expf(coef[1*ND+d]);
    float l2 = expf(coef[2*ND+d]), l3 = expf(coef[3*ND+d]);
    float c0=0.f, c1=0.f, c2=0.f, c3=0.f;
    int base = b*NS + k*CLEN;
    #pragma unroll 4
    for (int j = 0; j < CLEN; j++) {
        float4 p = d_proj[base + j];
        c0 = c0*l0 + p.x; c1 = c1*l1 + p.y;
        c2 = c2*l2 + p.z; c3 = c3*l3 + p.w;
    }
    d_end[(b*NCHUNK + k)*ND + d] = make_float4(c0, c1, c2, c3);
}

// pass3 with inlined chunk-combine: carry-in from d_end prefix
__global__ void hyena_pass3(const float* __restrict__ coef) {
    int tid = blockIdx.x * blockDim.x + threadIdx.x;
    int d = tid & (ND-1);
    int k = (tid >> 9) & (NCHUNK-1);
    int b = tid >> 14;
    float l0 = expf(coef[0*ND+d]), l1 = expf(coef[1*ND+d]);
    float l2 = expf(coef[2*ND+d]), l3 = expf(coef[3*ND+d]);
    float L0 = expf(coef[0*ND+d]*(float)CLEN), L1 = expf(coef[1*ND+d]*(float)CLEN);
    float L2 = expf(coef[2*ND+d]*(float)CLEN), L3 = expf(coef[3*ND+d]*(float)CLEN);
    float4 c = make_float4(0.f, 0.f, 0.f, 0.f);
    for (int j = 0; j < k; j++) {
        float4 e = d_end[(b*NCHUNK + j)*ND + d];
        c.x = c.x*L0 + e.x; c.y = c.y*L1 + e.y;
        c.z = c.z*L2 + e.z; c.w = c.w*L3 + e.w;
    }
    int base = b*NS + k*CLEN;
    #pragma unroll 4
    for (int j = 0; j < CLEN; j++) {
        float4 p = d_proj[base + j];
        c.x = c.x*l0 + p.x; c.y = c.y*l1 + p.y;
        c.z = c.z*l2 + p.z; c.w = c.w*l3 + p.w;
        size_t idx = (size_t)(base + j)*ND + d;
        d_h[idx] += c.x + c.y + c.z + c.w;
    }
}

// ---------------- LN2 (warp-per-token): h -> fp16 d_th -----------------------
__global__ void ln2_kernel(const float* __restrict__ w, const float* __restrict__ bta) {
    int wi = threadIdx.x >> 5, lane = threadIdx.x & 31;
    int t = blockIdx.x * 4 + wi;
    const float4* hrow = (const float4*)(d_h + (size_t)t * ND);
    float4 v[4];
    float sum = 0.f;
    #pragma unroll
    for (int j = 0; j < 4; j++) {
        v[j] = hrow[lane + j*32];
        sum += v[j].x + v[j].y + v[j].z + v[j].w;
    }
    float mu = warpReduceSum(sum) * (1.0f/ND);
    float sq = 0.f;
    #pragma unroll
    for (int j = 0; j < 4; j++) {
        float a0=v[j].x-mu, a1=v[j].y-mu, a2=v[j].z-mu, a3=v[j].w-mu;
        sq += a0*a0 + a1*a1 + a2*a2 + a3*a3;
    }
    float rs = rsqrtf(warpReduceSum(sq) * (1.0f/ND) + 1e-5f);
    size_t trow = (size_t)t * ND;
    #pragma unroll
    for (int j = 0; j < 4; j++) {
        int f4 = lane + j*32;
        float4 wv = ((const float4*)w)[f4];
        float4 bv = ((const float4*)bta)[f4];
        float r0=(v[j].x-mu)*rs*wv.x+bv.x, r1=(v[j].y-mu)*rs*wv.y+bv.y;
        float r2=(v[j].z-mu)*rs*wv.z+bv.z, r3=(v[j].w-mu)*rs*wv.w+bv.w;
        *(__half2*)(d_th + trow + f4*4    ) =
            __halves2half2(__float2half_rn(r0), __float2half_rn(r1));
        *(__half2*)(d_th + trow + f4*4 + 2) =
            __halves2half2(__float2half_rn(r2), __float2half_rn(r3));
    }
}

// ---------------- 2-product HMMA GEMM, 3-stage cp.async pipeline -------------
// MODE 0: gelu(acc+bias) -> Ch
// MODE 1: r = acc+bias+Cf; Cf=r; Ch=fp16(r)
// MODE 2: r = acc+bias+Cf; (no Cf write) Ch=fp16(r)
#define SAB   80
#define BUFB  (128*SAB)
#define STGB  (3*BUFB)      // 30720 per stage (Ah,Bh,Bl)
#define GSMEM (3*STGB)      // 92160, triple buffered

template<int MODE>
__global__ void __launch_bounds__(256, 2)
hgemm(const __half* __restrict__ Ah,
      const __half* __restrict__ Bh, const __half* __restrict__ Bl,
      const float* __restrict__ bias, int N, int K,
      float* __restrict__ Cf, __half* __restrict__ Ch)
{
    extern __shared__ char smem[];
    const int tid = threadIdx.x, lane = tid & 31, w = tid >> 5;
    const int wm = w >> 2, wn = w & 3;
    const int bx = blockIdx.x, by = blockIdx.y;
    const int nK = K >> 5;
    const uint32_t sb0 = smem_u32(smem);

    const uint32_t a_off = (uint32_t)(wm*64 + (lane & 7) + ((lane >> 3) & 1) * 8) * SAB
                         + ((lane >> 4) & 1) * 16;
    const uint32_t b_off = (uint32_t)(wn*32 + (lane & 7) + ((lane >> 4) & 1) * 8) * SAB
                         + ((lane >> 3) & 1) * 16;

    const int lr = tid >> 2, lc8 = tid & 3;
    #define LD_STAGE(s, kk) do {                                                 \
        uint32_t _b = sb0 + (s) * STGB;                                          \
        _Pragma("unroll")                                                        \
        for (int _i = 0; _i < 2; _i++) {                                         \
            int _r = lr + _i * 64;                                               \
            uint32_t _o = _r * SAB + lc8 * 16;                                   \
            size_t _ar = (size_t)(by*128 + _r) * K + (kk) + lc8*8;               \
            size_t _br = (size_t)(bx*128 + _r) * K + (kk) + lc8*8;               \
            cpasync16(_b           + _o, Ah + _ar);                              \
            cpasync16(_b +   BUFB  + _o, Bh + _br);                              \
            cpasync16(_b + 2*BUFB  + _o, Bl + _br);                              \
        }                                                                        \
        asm volatile("cp.async.commit_group;" ::: "memory");                     \
    } while (0)

    float acc[4][4][4];
    #pragma unroll
    for (int i = 0; i < 4; i++)
        #pragma unroll
        for (int j = 0; j < 4; j++)
            #pragma unroll
            for (int q = 0; q < 4; q++) acc[i][j][q] = 0.f;

    LD_STAGE(0, 0);
    LD_STAGE(1, 32);               // nK >= 2 always (K >= 64)

    int s_cur = 0;                 // stage index (avoids modulo)
    for (int kt = 0; kt < nK; kt++) {
        if (kt < nK-1) asm volatile("cp.async.wait_group 1;" ::: "memory");
        else           asm volatile("cp.async.wait_group 0;" ::: "memory");
        __syncthreads();
        if (kt + 2 < nK) {
            int s_nxt = s_cur + 2; if (s_nxt >= 3) s_nxt -= 3;
            LD_STAGE(s_nxt, (kt + 2) * 32);
        }

        const uint32_t st = sb0 + s_cur * STGB;
        #pragma unroll
        for (int ks = 0; ks < 2; ks++) {
            uint32_t bh[4][2], bl[4][2];
            #pragma unroll
            for (int nip = 0; nip < 2; nip++) {
                uint32_t ba = st + BUFB + b_off + nip * (16*SAB) + ks * 32;
                ldmx4(bh[2*nip][0], bh[2*nip][1], bh[2*nip+1][0], bh[2*nip+1][1], ba);
                ldmx4(bl[2*nip][0], bl[2*nip][1], bl[2*nip+1][0], bl[2*nip+1][1], ba + BUFB);
            }
            #pragma unroll
            for (int mi = 0; mi < 4; mi++) {
                uint32_t aa = st + a_off + mi * (16*SAB) + ks * 32;
                uint32_t a0,a1,a2,a3;
                ldmx4(a0, a1, a2, a3, aa);
                #pragma unroll
                for (int ni = 0; ni < 4; ni++) {
                    mma16816(acc[mi][ni], a0,a1,a2,a3, bh[ni][0], bh[ni][1]);
                    mma16816(acc[mi][ni], a0,a1,a2,a3, bl[ni][0], bl[ni][1]);
                }
            }
        }
        if (++s_cur == 3) s_cur = 0;
    }

    // epilogue
    const int gr = lane >> 2, gc = (lane & 3) * 2;
    const int row0 = by*128 + wm*64;
    const int col0 = bx*128 + wn*32;
    #pragma unroll
    for (int mi = 0; mi < 4; mi++)
        #pragma unroll
        for (int h2 = 0; h2 < 2; h2++) {
            int row = row0 + mi*16 + gr + h2*8;
            #pragma unroll
            for (int ni = 0; ni < 4; ni++) {
                int col = col0 + ni*8 + gc;
                size_t idx = (size_t)row * N + col;
                float v0 = acc[mi][ni][h2*2+0] + bias[col];
                float v1 = acc[mi][ni][h2*2+1] + bias[col+1];
                if (MODE == 0) {
                    v0 = gelu_exact(v0); v1 = gelu_exact(v1);
                } else {
                    float2 old = *(const float2*)(Cf + idx);
                    v0 += old.x; v1 += old.y;
                    if (MODE == 1) *(float2*)(Cf + idx) = make_float2(v0, v1);
                }
                *(__half2*)(Ch + idx) =
                    __halves2half2(__float2half_rn(v0), __float2half_rn(v1));
            }
        }
}

// ---------------- head (warp-per-token): logits via folded skW ---------------
__global__ void head_kernel(float* __restrict__ out) {
    int wi = threadIdx.x >> 5, lane = threadIdx.x & 31;
    int t = blockIdx.x * 4 + wi;
    float l0 = 0.f, l1 = 0.f, l2 = 0.f;
    #pragma unroll
    for (int l = 0; l < NLAYER; l++) {
        #pragma unroll
        for (int j = 0; j < 4; j++) {
            int d = (lane + j*32) * 4;
            size_t hb = (size_t)t*ND + d;
            __half2 p0 = *(const __half2*)(&d_hl4[l][hb]);
            __half2 p1 = *(const __half2*)(&d_hl4[l][hb + 2]);
            float vv[4] = { __half2float(p0.x), __half2float(p0.y),
                            __half2float(p1.x), __half2float(p1.y) };
            const float* wr = d_skW + (l*ND + d) * 3;
            #pragma unroll
            for (int i = 0; i < 4; i++) {
                l0 += vv[i]*wr[i*3+0]; l1 += vv[i]*wr[i*3+1]; l2 += vv[i]*wr[i*3+2];
            }
        }
    }
    l0 = warpReduceSum(l0); l1 = warpReduceSum(l1); l2 = warpReduceSum(l2);
    if (lane == 0) {
        l0 += d_cst[0]; l1 += d_cst[1]; l2 += d_cst[2];
        float m = fmaxf(l0, fmaxf(l1, l2));
        float e0 = expf(l0-m), e1 = expf(l1-m), e2 = expf(l2-m);
        float inv = 1.0f / (e0+e1+e2);
        out[t*3+0] = e0*inv; out[t*3+1] = e1*inv; out[t*3+2] = e2*inv;
    }
}

// ---------------- launcher ---------------------------------------------------
extern "C" void kernel_launch(void* const* d_in, const int* in_sizes, int n_in,
                              void* d_out, int out_size) {
    const float* x       = (const float*)d_in[0];
    const float* embed_w = (const float*)d_in[1];
    const float* embed_b = (const float*)d_in[2];
    const float* pe      = (const float*)d_in[3];
    const float* norm1_w = (const float*)d_in[4];
    const float* norm1_b = (const float*)d_in[5];
    const float* norm2_w = (const float*)d_in[6];
    const float* norm2_b = (const float*)d_in[7];
    const float* hy_proj = (const float*)d_in[8];
    const float* hy_coef = (const float*)d_in[9];
    const float* ffn_w1  = (const float*)d_in[10];
    const float* ffn_b1  = (const float*)d_in[11];
    const float* ffn_w2  = (const float*)d_in[12];
    const float* ffn_b2  = (const float*)d_in[13];
    const float* skip_w  = (const float*)d_in[14];
    const float* skip_b  = (const float*)d_in[15];
    const float* out_w   = (const float*)d_in[16];
    const float* out_b   = (const float*)d_in[17];
    float* out = (float*)d_out;

    float *hp;
    __half *thp, *ghp, *w1h, *w1l, *w2h, *w2l, *hl4;
    cudaGetSymbolAddress((void**)&hp,  d_h);
    cudaGetSymbolAddress((void**)&thp, d_th);
    cudaGetSymbolAddress((void**)&ghp, d_gh);
    cudaGetSymbolAddress((void**)&hl4, d_hl4);
    cudaGetSymbolAddress((void**)&w1h, d_w1h); cudaGetSymbolAddress((void**)&w1l, d_w1l);
    cudaGetSymbolAddress((void**)&w2h, d_w2h); cudaGetSymbolAddress((void**)&w2l, d_w2l);

    cudaFuncSetAttribute(hgemm<0>, cudaFuncAttributeMaxDynamicSharedMemorySize, GSMEM);
    cudaFuncSetAttribute(hgemm<1>, cudaFuncAttributeMaxDynamicSharedMemorySize, GSMEM);
    cudaFuncSetAttribute(hgemm<2>, cudaFuncAttributeMaxDynamicSharedMemorySize, GSMEM);

    // weight prep (captured in graph)
    wsplitT<<<dim3(NF/32, ND/32, NLAYER), dim3(32,8)>>>(ffn_w1, w1h, w1l, ND, NF);
    wsplitT<<<dim3(ND/32, NF/32, NLAYER), dim3(32,8)>>>(ffn_w2, w2h, w2l, NF, ND);
    skw_prep<<<257, 256>>>(skip_w, skip_b, out_w, out_b);

    embed_kernel<<<NS, 128>>>(x, embed_w, embed_b, pe);

    for (int l = 0; l < NLAYER; l++) {
        const float* coef = hy_coef + (size_t)l*NO*ND;
        ln1_proj_kernel<<<NT/4, 128>>>(norm1_w + l*ND, norm1_b + l*ND,
                                       hy_proj + (size_t)l*NO*ND);
        hyena_pass1<<<(NB*NCHUNK*ND)/256, 256>>>(coef);
        hyena_pass3<<<(NB*NCHUNK*ND)/256, 256>>>(coef);
        ln2_kernel<<<NT/4, 128>>>(norm2_w + l*ND, norm2_b + l*ND);

        // FFN GEMM1: g = gelu(tmp @ w1 + b1)
        hgemm<0><<<dim3(NF/128, NT/128), 256, GSMEM>>>(
            thp, w1h + (size_t)l*NF*ND, w1l + (size_t)l*NF*ND,
            ffn_b1 + (size_t)l*NF, NF, ND, nullptr, ghp);
        // FFN GEMM2: h = g @ w2 + b2 + h; store fp16 h_l for head
        if (l < NLAYER-1)
            hgemm<1><<<dim3(ND/128, NT/128), 256, GSMEM>>>(
                ghp, w2h + (size_t)l*ND*NF, w2l + (size_t)l*ND*NF,
                ffn_b2 + (size_t)l*ND, ND, NF, hp, hl4 + (size_t)l*NT*ND);
        else   // last layer: d_h never read again -> skip the fp32 writeback
            hgemm<2><<<dim3(ND/128, NT/128), 256, GSMEM>>>(
                ghp, w2h + (size_t)l*ND*NF, w2l + (size_t)l*ND*NF,
                ffn_b2 + (size_t)l*ND, ND, NF, hp, hl4 + (size_t)l*NT*ND);
    }

    head_kernel<<<NT/4, 128>>>(out);
}

// round 15
// speedup vs baseline: 1.2360x; 1.0131x over previous
#include <cuda_runtime.h>
#include <cuda_fp16.h>
#include <math.h>
#include <stdint.h>

// Problem constants
#define NB 4
#define NS 4096
#define ND 512
#define NO 4
#define NLAYER 4
#define NF 2048
#define NT (NB*NS)
#define NCHUNK 32
#define CLEN 128

// ---------------- scratch (static device globals) ----------------------------
__device__ __align__(256) float  d_h[(size_t)NT * ND];
__device__ __align__(256) float4 d_proj[NT];
__device__ __align__(256) float4 d_end[NB * NCHUNK * ND];
// fp16 activation buffers
__device__ __align__(256) __half d_th[(size_t)NT*ND];
__device__ __align__(256) __half d_gh[(size_t)NT*NF];
__device__ __align__(256) __half d_hl4[NLAYER][(size_t)NT*ND];  // per-layer h (fp16)
// transposed+split weights: [N,K] K-major, hi/lo
__device__ __align__(256) __half d_w1h[(size_t)NLAYER*NF*ND], d_w1l[(size_t)NLAYER*NF*ND];
__device__ __align__(256) __half d_w2h[(size_t)NLAYER*ND*NF], d_w2l[(size_t)NLAYER*ND*NF];
// folded head weights
__device__ __align__(256) float d_skW[NLAYER*ND*3];
__device__ __align__(256) float d_cst[3];

// ---------------- helpers ----------------------------------------------------
__device__ __forceinline__ uint32_t smem_u32(const void* p) {
    uint32_t a;
    asm("{ .reg .u64 t; cvta.to.shared.u64 t, %1; cvt.u32.u64 %0, t; }" : "=r"(a) : "l"(p));
    return a;
}
__device__ __forceinline__ void cpasync16(uint32_t s, const void* g) {
    asm volatile("cp.async.cg.shared.global [%0], [%1], 16;" :: "r"(s), "l"(g));
}
__device__ __forceinline__ void ldmx4(uint32_t& r0, uint32_t& r1, uint32_t& r2,
                                      uint32_t& r3, uint32_t addr) {
    asm volatile("ldmatrix.sync.aligned.m8n8.x4.shared.b16 {%0,%1,%2,%3}, [%4];"
        : "=r"(r0), "=r"(r1), "=r"(r2), "=r"(r3) : "r"(addr));
}
__device__ __forceinline__ void split2h(float v, __half& h, __half& l) {
    h = __float2half_rn(v);
    l = __float2half_rn(v - __half2float(h));
}
__device__ __forceinline__ float gelu_exact(float x) {
    return 0.5f * x * (1.0f + erff(x * 0.70710678118654752440f));
}
__device__ __forceinline__ float warpReduceSum(float v) {
    #pragma unroll
    for (int o = 16; o > 0; o >>= 1) v += __shfl_xor_sync(0xffffffffu, v, o);
    return v;
}
__device__ __forceinline__ void mma16816(float* c, uint32_t a0, uint32_t a1,
                                         uint32_t a2, uint32_t a3,
                                         uint32_t b0, uint32_t b1) {
    asm volatile("mma.sync.aligned.m16n8k16.row.col.f32.f16.f16.f32 "
        "{%0,%1,%2,%3}, {%4,%5,%6,%7}, {%8,%9}, {%0,%1,%2,%3};"
        : "+f"(c[0]), "+f"(c[1]), "+f"(c[2]), "+f"(c[3])
        : "r"(a0), "r"(a1), "r"(a2), "r"(a3), "r"(b0), "r"(b1));
}

// ---------------- weight transpose + split (batched over layers) -------------
__global__ void wsplitT(const float* __restrict__ w, __half* __restrict__ hi,
                        __half* __restrict__ lo, int K, int N) {
    __shared__ float t[32][33];
    size_t loff = (size_t)blockIdx.z * K * N;
    int n0 = blockIdx.x * 32, k0 = blockIdx.y * 32;
    int tx = threadIdx.x, ty = threadIdx.y;   // (32,8)
    #pragma unroll
    for (int j = 0; j < 4; j++) {
        int r = ty * 4 + j;
        t[r][tx] = w[loff + (size_t)(k0 + r) * N + n0 + tx];
    }
    __syncthreads();
    #pragma unroll
    for (int j = 0; j < 4; j++) {
        int r = ty * 4 + j;
        float v = t[tx][r];
        __half h, l; split2h(v, h, l);
        size_t oi = loff + (size_t)(n0 + r) * K + k0 + tx;
        hi[oi] = h; lo[oi] = l;
    }
}

// ---------------- fold skip weights + constant (single launch) ---------------
__global__ void skw_prep(const float* __restrict__ skip_w, const float* __restrict__ skip_b,
                         const float* __restrict__ ow, const float* __restrict__ ob) {
    int lane = threadIdx.x & 31;
    if (blockIdx.x < 256) {
        int w = (blockIdx.x * blockDim.x + threadIdx.x) >> 5;
        int l = w >> 9, d = w & (ND-1);
        const float* wr = skip_w + ((size_t)l * ND + d) * ND;
        float s0 = 0.f, s1 = 0.f, s2 = 0.f;
        for (int n = lane; n < ND; n += 32) {
            float v = wr[n];
            const float* o = ow + n * 3;
            s0 += v * o[0]; s1 += v * o[1]; s2 += v * o[2];
        }
        s0 = warpReduceSum(s0); s1 = warpReduceSum(s1); s2 = warpReduceSum(s2);
        if (lane == 0) {
            float* dst = d_skW + (l * ND + d) * 3;
            dst[0] = s0; dst[1] = s1; dst[2] = s2;
        }
    } else {
        __shared__ float part[3][2];
        int wid = threadIdx.x >> 5;
        if (wid < 6) {
            int j = wid % 3, chunk = wid / 3;
            float s = 0.f;
            for (int i = lane; i < 1024; i += 32) {
                int ln = chunk * 1024 + i;
                s += skip_b[ln] * ow[(ln & (ND-1)) * 3 + j];
            }
            s = warpReduceSum(s);
            if (lane == 0) part[j][chunk] = s;
        }
        __syncthreads();
        if (threadIdx.x < 3)
            d_cst[threadIdx.x] = ob[threadIdx.x] + part[threadIdx.x][0] + part[threadIdx.x][1];
    }
}

// ---------------- embed (block per s) ----------------------------------------
__global__ void embed_kernel(const float* __restrict__ x, const float* __restrict__ ew,
                             const float* __restrict__ eb, const float* __restrict__ pe) {
    int s = blockIdx.x, tid = threadIdx.x;
    float4 e0 = ((const float4*)(ew        ))[tid];
    float4 e1 = ((const float4*)(ew +   ND))[tid];
    float4 e2 = ((const float4*)(ew + 2*ND))[tid];
    float4 e3 = ((const float4*)(ew + 3*ND))[tid];
    float4 bb = ((const float4*)eb)[tid];
    float4 pp = ((const float4*)(pe + (size_t)s*ND))[tid];
    float bx = bb.x + pp.x, by = bb.y + pp.y, bz = bb.z + pp.z, bw = bb.w + pp.w;
    #pragma unroll
    for (int b = 0; b < NB; b++) {
        int t = b*NS + s;
        float x0 = x[t*4+0], x1 = x[t*4+1], x2 = x[t*4+2], x3 = x[t*4+3];
        float4 r;
        r.x = x0*e0.x + x1*e1.x + x2*e2.x + x3*e3.x + bx;
        r.y = x0*e0.y + x1*e1.y + x2*e2.y + x3*e3.y + by;
        r.z = x0*e0.z + x1*e1.z + x2*e2.z + x3*e3.z + bz;
        r.w = x0*e0.w + x1*e1.w + x2*e2.w + x3*e3.w + bw;
        ((float4*)(d_h + (size_t)t*ND))[tid] = r;
    }
}

// ---------------- fused LN1 + hyena projection (warp-per-token) --------------
__global__ void ln1_proj_kernel(const float* __restrict__ w, const float* __restrict__ bta,
                                const float* __restrict__ P) {
    int wi = threadIdx.x >> 5, lane = threadIdx.x & 31;
    int t = blockIdx.x * 4 + wi;
    const float4* hrow = (const float4*)(d_h + (size_t)t * ND);
    float4 v[4];
    float sum = 0.f;
    #pragma unroll
    for (int j = 0; j < 4; j++) {
        v[j] = hrow[lane + j*32];
        sum += v[j].x + v[j].y + v[j].z + v[j].w;
    }
    float mu = warpReduceSum(sum) * (1.0f/ND);
    float sq = 0.f;
    #pragma unroll
    for (int j = 0; j < 4; j++) {
        float a0=v[j].x-mu, a1=v[j].y-mu, a2=v[j].z-mu, a3=v[j].w-mu;
        sq += a0*a0 + a1*a1 + a2*a2 + a3*a3;
    }
    float rs = rsqrtf(warpReduceSum(sq) * (1.0f/ND) + 1e-5f);
    float p0=0.f, p1=0.f, p2=0.f, p3=0.f;
    #pragma unroll
    for (int j = 0; j < 4; j++) {
        int f4 = lane + j*32;
        float4 wv = ((const float4*)w)[f4];
        float4 bv = ((const float4*)bta)[f4];
        float n0=(v[j].x-mu)*rs*wv.x+bv.x, n1=(v[j].y-mu)*rs*wv.y+bv.y;
        float n2=(v[j].z-mu)*rs*wv.z+bv.z, n3=(v[j].w-mu)*rs*wv.w+bv.w;
        float4 q0 = ((const float4*)(P       ))[f4];
        float4 q1 = ((const float4*)(P +   ND))[f4];
        float4 q2 = ((const float4*)(P + 2*ND))[f4];
        float4 q3 = ((const float4*)(P + 3*ND))[f4];
        p0 += n0*q0.x + n1*q0.y + n2*q0.z + n3*q0.w;
        p1 += n0*q1.x + n1*q1.y + n2*q1.z + n3*q1.w;
        p2 += n0*q2.x + n1*q2.y + n2*q2.z + n3*q2.w;
        p3 += n0*q3.x + n1*q3.y + n2*q3.z + n3*q3.w;
    }
    p0 = warpReduceSum(p0); p1 = warpReduceSum(p1);
    p2 = warpReduceSum(p2); p3 = warpReduceSum(p3);
    if (lane == 0) d_proj[t] = make_float4(p0, p1, p2, p3);
}

// ---------------- hyena scan -------------------------------------------------
__global__ void hyena_pass1(const float* __restrict__ coef) {
    int tid = blockIdx.x * blockDim.x + threadIdx.x;
    int d = tid & (ND-1);
    int k = (tid >> 9) & (NCHUNK-1);
    int b = tid >> 14;
    float l0 = expf(coef[0*ND+d]), l1 = expf(coef[1*ND+d]);
    float l2 = expf(coef[2*ND+d]), l3 = expf(coef[3*ND+d]);
    float c0=0.f, c1=0.f, c2=0.f, c3=0.f;
    int base = b*NS + k*CLEN;
    #pragma unroll 4
    for (int j = 0; j < CLEN; j++) {
        float4 p = d_proj[base + j];
        c0 = c0*l0 + p.x; c1 = c1*l1 + p.y;
        c2 = c2*l2 + p.z; c3 = c3*l3 + p.w;
    }
    d_end[(b*NCHUNK + k)*ND + d] = make_float4(c0, c1, c2, c3);
}

__global__ void hyena_pass3(const float* __restrict__ coef) {
    int tid = blockIdx.x * blockDim.x + threadIdx.x;
    int d = tid & (ND-1);
    int k = (tid >> 9) & (NCHUNK-1);
    int b = tid >> 14;
    float l0 = expf(coef[0*ND+d]), l1 = expf(coef[1*ND+d]);
    float l2 = expf(coef[2*ND+d]), l3 = expf(coef[3*ND+d]);
    float L0 = expf(coef[0*ND+d]*(float)CLEN), L1 = expf(coef[1*ND+d]*(float)CLEN);
    float L2 = expf(coef[2*ND+d]*(float)CLEN), L3 = expf(coef[3*ND+d]*(float)CLEN);
    float4 c = make_float4(0.f, 0.f, 0.f, 0.f);
    for (int j = 0; j < k; j++) {
        float4 e = d_end[(b*NCHUNK + j)*ND + d];
        c.x = c.x*L0 + e.x; c.y = c.y*L1 + e.y;
        c.z = c.z*L2 + e.z; c.w = c.w*L3 + e.w;
    }
    int base = b*NS + k*CLEN;
    #pragma unroll 4
    for (int j = 0; j < CLEN; j++) {
        float4 p = d_proj[base + j];
        c.x = c.x*l0 + p.x; c.y = c.y*l1 + p.y;
        c.z = c.z*l2 + p.z; c.w = c.w*l3 + p.w;
        size_t idx = (size_t)(base + j)*ND + d;
        d_h[idx] += c.x + c.y + c.z + c.w;
    }
}

// ---------------- LN2 (warp-per-token): h -> fp16 d_th -----------------------
__global__ void ln2_kernel(const float* __restrict__ w, const float* __restrict__ bta) {
    int wi = threadIdx.x >> 5, lane = threadIdx.x & 31;
    int t = blockIdx.x * 4 + wi;
    const float4* hrow = (const float4*)(d_h + (size_t)t * ND);
    float4 v[4];
    float sum = 0.f;
    #pragma unroll
    for (int j = 0; j < 4; j++) {
        v[j] = hrow[lane + j*32];
        sum += v[j].x + v[j].y + v[j].z + v[j].w;
    }
    float mu = warpReduceSum(sum) * (1.0f/ND);
    float sq = 0.f;
    #pragma unroll
    for (int j = 0; j < 4; j++) {
        float a0=v[j].x-mu, a1=v[j].y-mu, a2=v[j].z-mu, a3=v[j].w-mu;
        sq += a0*a0 + a1*a1 + a2*a2 + a3*a3;
    }
    float rs = rsqrtf(warpReduceSum(sq) * (1.0f/ND) + 1e-5f);
    size_t trow = (size_t)t * ND;
    #pragma unroll
    for (int j = 0; j < 4; j++) {
        int f4 = lane + j*32;
        float4 wv = ((const float4*)w)[f4];
        float4 bv = ((const float4*)bta)[f4];
        float r0=(v[j].x-mu)*rs*wv.x+bv.x, r1=(v[j].y-mu)*rs*wv.y+bv.y;
        float r2=(v[j].z-mu)*rs*wv.z+bv.z, r3=(v[j].w-mu)*rs*wv.w+bv.w;
        *(__half2*)(d_th + trow + f4*4    ) =
            __halves2half2(__float2half_rn(r0), __float2half_rn(r1));
        *(__half2*)(d_th + trow + f4*4 + 2) =
            __halves2half2(__float2half_rn(r2), __float2half_rn(r3));
    }
}

// ---------------- 2-product HMMA GEMM, 128x128 tile, 3-stage (GEMM1) ---------
#define SAB   80
#define BUFB  (128*SAB)
#define STGB  (3*BUFB)
#define GSMEM (3*STGB)

template<int MODE>
__global__ void __launch_bounds__(256, 2)
hgemm(const __half* __restrict__ Ah,
      const __half* __restrict__ Bh, const __half* __restrict__ Bl,
      const float* __restrict__ bias, int N, int K,
      float* __restrict__ Cf, __half* __restrict__ Ch)
{
    extern __shared__ char smem[];
    const int tid = threadIdx.x, lane = tid & 31, w = tid >> 5;
    const int wm = w >> 2, wn = w & 3;
    const int bx = blockIdx.x, by = blockIdx.y;
    const int nK = K >> 5;
    const uint32_t sb0 = smem_u32(smem);

    const uint32_t a_off = (uint32_t)(wm*64 + (lane & 7) + ((lane >> 3) & 1) * 8) * SAB
                         + ((lane >> 4) & 1) * 16;
    const uint32_t b_off = (uint32_t)(wn*32 + (lane & 7) + ((lane >> 4) & 1) * 8) * SAB
                         + ((lane >> 3) & 1) * 16;

    const int lr = tid >> 2, lc8 = tid & 3;
    #define LD_STAGE(s, kk) do {                                                 \
        uint32_t _b = sb0 + (s) * STGB;                                          \
        _Pragma("unroll")                                                        \
        for (int _i = 0; _i < 2; _i++) {                                         \
            int _r = lr + _i * 64;                                               \
            uint32_t _o = _r * SAB + lc8 * 16;                                   \
            size_t _ar = (size_t)(by*128 + _r) * K + (kk) + lc8*8;               \
            size_t _br = (size_t)(bx*128 + _r) * K + (kk) + lc8*8;               \
            cpasync16(_b           + _o, Ah + _ar);                              \
            cpasync16(_b +   BUFB  + _o, Bh + _br);                              \
            cpasync16(_b + 2*BUFB  + _o, Bl + _br);                              \
        }                                                                        \
        asm volatile("cp.async.commit_group;" ::: "memory");                     \
    } while (0)

    float acc[4][4][4];
    #pragma unroll
    for (int i = 0; i < 4; i++)
        #pragma unroll
        for (int j = 0; j < 4; j++)
            #pragma unroll
            for (int q = 0; q < 4; q++) acc[i][j][q] = 0.f;

    LD_STAGE(0, 0);
    LD_STAGE(1, 32);

    int s_cur = 0;
    for (int kt = 0; kt < nK; kt++) {
        if (kt < nK-1) asm volatile("cp.async.wait_group 1;" ::: "memory");
        else           asm volatile("cp.async.wait_group 0;" ::: "memory");
        __syncthreads();
        if (kt + 2 < nK) {
            int s_nxt = s_cur + 2; if (s_nxt >= 3) s_nxt -= 3;
            LD_STAGE(s_nxt, (kt + 2) * 32);
        }

        const uint32_t st = sb0 + s_cur * STGB;
        #pragma unroll
        for (int ks = 0; ks < 2; ks++) {
            uint32_t bh[4][2], bl[4][2];
            #pragma unroll
            for (int nip = 0; nip < 2; nip++) {
                uint32_t ba = st + BUFB + b_off + nip * (16*SAB) + ks * 32;
                ldmx4(bh[2*nip][0], bh[2*nip][1], bh[2*nip+1][0], bh[2*nip+1][1], ba);
                ldmx4(bl[2*nip][0], bl[2*nip][1], bl[2*nip+1][0], bl[2*nip+1][1], ba + BUFB);
            }
            #pragma unroll
            for (int mi = 0; mi < 4; mi++) {
                uint32_t aa = st + a_off + mi * (16*SAB) + ks * 32;
                uint32_t a0,a1,a2,a3;
                ldmx4(a0, a1, a2, a3, aa);
                #pragma unroll
                for (int ni = 0; ni < 4; ni++) {
                    mma16816(acc[mi][ni], a0,a1,a2,a3, bh[ni][0], bh[ni][1]);
                    mma16816(acc[mi][ni], a0,a1,a2,a3, bl[ni][0], bl[ni][1]);
                }
            }
        }
        if (++s_cur == 3) s_cur = 0;
    }

    const int gr = lane >> 2, gc = (lane & 3) * 2;
    const int row0 = by*128 + wm*64;
    const int col0 = bx*128 + wn*32;
    #pragma unroll
    for (int mi = 0; mi < 4; mi++)
        #pragma unroll
        for (int h2 = 0; h2 < 2; h2++) {
            int row = row0 + mi*16 + gr + h2*8;
            #pragma unroll
            for (int ni = 0; ni < 4; ni++) {
                int col = col0 + ni*8 + gc;
                size_t idx = (size_t)row * N + col;
                float v0 = acc[mi][ni][h2*2+0] + bias[col];
                float v1 = acc[mi][ni][h2*2+1] + bias[col+1];
                if (MODE == 0) {
                    v0 = gelu_exact(v0); v1 = gelu_exact(v1);
                } else {
                    float2 old = *(const float2*)(Cf + idx);
                    v0 += old.x; v1 += old.y;
                    if (MODE == 1) *(float2*)(Cf + idx) = make_float2(v0, v1);
                }
                *(__half2*)(Ch + idx) =
                    __halves2half2(__float2half_rn(v0), __float2half_rn(v1));
            }
        }
}

// ---------------- 64x64-tile GEMM (GEMM2): 128 thr, 4 CTA/SM, 3-stage --------
// Same per-element accumulation order as hgemm -> bitwise-identical results.
#define B64   (64*SAB)       // 5120 per buffer
#define STG64 (3*B64)        // 15360 per stage
#define GS64  (3*STG64)      // 46080

template<int MODE>
__global__ void __launch_bounds__(128, 4)
hgemm64(const __half* __restrict__ Ah,
        const __half* __restrict__ Bh, const __half* __restrict__ Bl,
        const float* __restrict__ bias, int N, int K,
        float* __restrict__ Cf, __half* __restrict__ Ch)
{
    extern __shared__ char smem[];
    const int tid = threadIdx.x, lane = tid & 31, w = tid >> 5;
    const int wm = w >> 1, wn = w & 1;        // 2 x 2 warp grid, warp tile 32x32
    const int bx = blockIdx.x, by = blockIdx.y;
    const int nK = K >> 5;
    const uint32_t sb0 = smem_u32(smem);

    const uint32_t a_off = (uint32_t)(wm*32 + (lane & 7) + ((lane >> 3) & 1) * 8) * SAB
                         + ((lane >> 4) & 1) * 16;
    const uint32_t b_off = (uint32_t)(wn*32 + (lane & 7) + ((lane >> 4) & 1) * 8) * SAB
                         + ((lane >> 3) & 1) * 16;

    const int lr = tid >> 2, lc8 = tid & 3;   // 32 rows x 4 chunks; x2 rows loop
    #define LD_STAGE64(s, kk) do {                                               \
        uint32_t _b = sb0 + (s) * STG64;                                         \
        _Pragma("unroll")                                                        \
        for (int _i = 0; _i < 2; _i++) {                                         \
            int _r = lr + _i * 32;                                               \
            uint32_t _o = _r * SAB + lc8 * 16;                                   \
            size_t _ar = (size_t)(by*64 + _r) * K + (kk) + lc8*8;                \
            size_t _br = (size_t)(bx*64 + _r) * K + (kk) + lc8*8;                \
            cpasync16(_b          + _o, Ah + _ar);                               \
            cpasync16(_b +  B64   + _o, Bh + _br);                               \
            cpasync16(_b + 2*B64  + _o, Bl + _br);                               \
        }                                                                        \
        asm volatile("cp.async.commit_group;" ::: "memory");                     \
    } while (0)

    float acc[2][4][4];
    #pragma unroll
    for (int i = 0; i < 2; i++)
        #pragma unroll
        for (int j = 0; j < 4; j++)
            #pragma unroll
            for (int q = 0; q < 4; q++) acc[i][j][q] = 0.f;

    LD_STAGE64(0, 0);
    LD_STAGE64(1, 32);

    int s_cur = 0;
    for (int kt = 0; kt < nK; kt++) {
        if (kt < nK-1) asm volatile("cp.async.wait_group 1;" ::: "memory");
        else           asm volatile("cp.async.wait_group 0;" ::: "memory");
        __syncthreads();
        if (kt + 2 < nK) {
            int s_nxt = s_cur + 2; if (s_nxt >= 3) s_nxt -= 3;
            LD_STAGE64(s_nxt, (kt + 2) * 32);
        }

        const uint32_t st = sb0 + s_cur * STG64;
        #pragma unroll
        for (int ks = 0; ks < 2; ks++) {
            uint32_t bh[4][2], bl[4][2];
            #pragma unroll
            for (int nip = 0; nip < 2; nip++) {
                uint32_t ba = st + B64 + b_off + nip * (16*SAB) + ks * 32;
                ldmx4(bh[2*nip][0], bh[2*nip][1], bh[2*nip+1][0], bh[2*nip+1][1], ba);
                ldmx4(bl[2*nip][0], bl[2*nip][1], bl[2*nip+1][0], bl[2*nip+1][1], ba + B64);
            }
            #pragma unroll
            for (int mi = 0; mi < 2; mi++) {
                uint32_t aa = st + a_off + mi * (16*SAB) + ks * 32;
                uint32_t a0,a1,a2,a3;
                ldmx4(a0, a1, a2, a3, aa);
                #pragma unroll
                for (int ni = 0; ni < 4; ni++) {
                    mma16816(acc[mi][ni], a0,a1,a2,a3, bh[ni][0], bh[ni][1]);
                    mma16816(acc[mi][ni], a0,a1,a2,a3, bl[ni][0], bl[ni][1]);
                }
            }
        }
        if (++s_cur == 3) s_cur = 0;
    }

    const int gr = lane >> 2, gc = (lane & 3) * 2;
    const int row0 = by*64 + wm*32;
    const int col0 = bx*64 + wn*32;
    #pragma unroll
    for (int mi = 0; mi < 2; mi++)
        #pragma unroll
        for (int h2 = 0; h2 < 2; h2++) {
            int row = row0 + mi*16 + gr + h2*8;
            #pragma unroll
            for (int ni = 0; ni < 4; ni++) {
                int col = col0 + ni*8 + gc;
                size_t idx = (size_t)row * N + col;
                float v0 = acc[mi][ni][h2*2+0] + bias[col];
                float v1 = acc[mi][ni][h2*2+1] + bias[col+1];
                if (MODE == 0) {
                    v0 = gelu_exact(v0); v1 = gelu_exact(v1);
                } else {
                    float2 old = *(const float2*)(Cf + idx);
                    v0 += old.x; v1 += old.y;
                    if (MODE == 1) *(float2*)(Cf + idx) = make_float2(v0, v1);
                }
                *(__half2*)(Ch + idx) =
                    __halves2half2(__float2half_rn(v0), __float2half_rn(v1));
            }
        }
}

// ---------------- head (warp-per-token): logits via folded skW ---------------
__global__ void head_kernel(float* __restrict__ out) {
    int wi = threadIdx.x >> 5, lane = threadIdx.x & 31;
    int t = blockIdx.x * 4 + wi;
    float l0 = 0.f, l1 = 0.f, l2 = 0.f;
    #pragma unroll
    for (int l = 0; l < NLAYER; l++) {
        #pragma unroll
        for (int j = 0; j < 4; j++) {
            int d = (lane + j*32) * 4;
            size_t hb = (size_t)t*ND + d;
            __half2 p0 = *(const __half2*)(&d_hl4[l][hb]);
            __half2 p1 = *(const __half2*)(&d_hl4[l][hb + 2]);
            float vv[4] = { __half2float(p0.x), __half2float(p0.y),
                            __half2float(p1.x), __half2float(p1.y) };
            const float* wr = d_skW + (l*ND + d) * 3;
            #pragma unroll
            for (int i = 0; i < 4; i++) {
                l0 += vv[i]*wr[i*3+0]; l1 += vv[i]*wr[i*3+1]; l2 += vv[i]*wr[i*3+2];
            }
        }
    }
    l0 = warpReduceSum(l0); l1 = warpReduceSum(l1); l2 = warpReduceSum(l2);
    if (lane == 0) {
        l0 += d_cst[0]; l1 += d_cst[1]; l2 += d_cst[2];
        float m = fmaxf(l0, fmaxf(l1, l2));
        float e0 = expf(l0-m), e1 = expf(l1-m), e2 = expf(l2-m);
        float inv = 1.0f / (e0+e1+e2);
        out[t*3+0] = e0*inv; out[t*3+1] = e1*inv; out[t*3+2] = e2*inv;
    }
}

// ---------------- launcher ---------------------------------------------------
extern "C" void kernel_launch(void* const* d_in, const int* in_sizes, int n_in,
                              void* d_out, int out_size) {
    const float* x       = (const float*)d_in[0];
    const float* embed_w = (const float*)d_in[1];
    const float* embed_b = (const float*)d_in[2];
    const float* pe      = (const float*)d_in[3];
    const float* norm1_w = (const float*)d_in[4];
    const float* norm1_b = (const float*)d_in[5];
    const float* norm2_w = (const float*)d_in[6];
    const float* norm2_b = (const float*)d_in[7];
    const float* hy_proj = (const float*)d_in[8];
    const float* hy_coef = (const float*)d_in[9];
    const float* ffn_w1  = (const float*)d_in[10];
    const float* ffn_b1  = (const float*)d_in[11];
    const float* ffn_w2  = (const float*)d_in[12];
    const float* ffn_b2  = (const float*)d_in[13];
    const float* skip_w  = (const float*)d_in[14];
    const float* skip_b  = (const float*)d_in[15];
    const float* out_w   = (const float*)d_in[16];
    const float* out_b   = (const float*)d_in[17];
    float* out = (float*)d_out;

    float *hp;
    __half *thp, *ghp, *w1h, *w1l, *w2h, *w2l, *hl4;
    cudaGetSymbolAddress((void**)&hp,  d_h);
    cudaGetSymbolAddress((void**)&thp, d_th);
    cudaGetSymbolAddress((void**)&ghp, d_gh);
    cudaGetSymbolAddress((void**)&hl4, d_hl4);
    cudaGetSymbolAddress((void**)&w1h, d_w1h); cudaGetSymbolAddress((void**)&w1l, d_w1l);
    cudaGetSymbolAddress((void**)&w2h, d_w2h); cudaGetSymbolAddress((void**)&w2l, d_w2l);

    cudaFuncSetAttribute(hgemm<0>, cudaFuncAttributeMaxDynamicSharedMemorySize, GSMEM);
    cudaFuncSetAttribute(hgemm64<1>, cudaFuncAttributeMaxDynamicSharedMemorySize, GS64);
    cudaFuncSetAttribute(hgemm64<2>, cudaFuncAttributeMaxDynamicSharedMemorySize, GS64);

    // weight prep (captured in graph)
    wsplitT<<<dim3(NF/32, ND/32, NLAYER), dim3(32,8)>>>(ffn_w1, w1h, w1l, ND, NF);
    wsplitT<<<dim3(ND/32, NF/32, NLAYER), dim3(32,8)>>>(ffn_w2, w2h, w2l, NF, ND);
    skw_prep<<<257, 256>>>(skip_w, skip_b, out_w, out_b);

    embed_kernel<<<NS, 128>>>(x, embed_w, embed_b, pe);

    for (int l = 0; l < NLAYER; l++) {
        const float* coef = hy_coef + (size_t)l*NO*ND;
        ln1_proj_kernel<<<NT/4, 128>>>(norm1_w + l*ND, norm1_b + l*ND,
                                       hy_proj + (size_t)l*NO*ND);
        hyena_pass1<<<(NB*NCHUNK*ND)/256, 256>>>(coef);
        hyena_pass3<<<(NB*NCHUNK*ND)/256, 256>>>(coef);
        ln2_kernel<<<NT/4, 128>>>(norm2_w + l*ND, norm2_b + l*ND);

        // FFN GEMM1 (128x128 tiles, near-perfect waves)
        hgemm<0><<<dim3(NF/128, NT/128), 256, GSMEM>>>(
            thp, w1h + (size_t)l*NF*ND, w1l + (size_t)l*NF*ND,
            ffn_b1 + (size_t)l*NF, NF, ND, nullptr, ghp);
        // FFN GEMM2 (64x64 tiles, 4 CTA/SM -> fine-grained waves)
        if (l < NLAYER-1)
            hgemm64<1><<<dim3(ND/64, NT/64), 128, GS64>>>(
                ghp, w2h + (size_t)l*ND*NF, w2l + (size_t)l*ND*NF,
                ffn_b2 + (size_t)l*ND, ND, NF, hp, hl4 + (size_t)l*NT*ND);
        else
            hgemm64<2><<<dim3(ND/64, NT/64), 128, GS64>>>(
                ghp, w2h + (size_t)l*ND*NF, w2l + (size_t)l*ND*NF,
                ffn_b2 + (size_t)l*ND, ND, NF, hp, hl4 + (size_t)l*NT*ND);
    }

    head_kernel<<<NT/4, 128>>>(out);
}